// round 3
// baseline (speedup 1.0000x reference)
#include <cuda_runtime.h>

#define N_NODES 50000

// ---- scratch (static __device__ — no allocations allowed) ----
__device__ __align__(16) float4 g_agg1[N_NODES * 32];   // [N,128] sum of x[src] per dst
__device__ __align__(16) float4 g_aggp[N_NODES * 32];   // [N,128] sum of p[src] per dst
__device__ __align__(16) float4 g_p   [N_NODES * 32];   // h @ W2_l.T
__device__ __align__(16) float4 g_r2  [N_NODES * 32];   // h @ W2_r.T
__device__ float  g_deg [N_NODES];
__device__ __align__(16) float g_WT1 [256 * 256];  // [k][t]; k<128 -> W1_l, else W1_r
__device__ __align__(16) float g_WT2 [256 * 256];  // [k][j]; j<128 -> W2_l (p), else W2_r (r2)

// ---- zero the accumulators ----
__global__ void zero_kernel() {
    int i = blockIdx.x * blockDim.x + threadIdx.x;
    float4 z = make_float4(0.f, 0.f, 0.f, 0.f);
    if (i < N_NODES * 32) { g_agg1[i] = z; g_aggp[i] = z; }
    if (i < N_NODES) g_deg[i] = 0.f;
}

// ---- transpose/pack weights for coalesced GEMM reads ----
__global__ void prep_weights(const float* __restrict__ W1l, const float* __restrict__ W1r,
                             const float* __restrict__ W2l, const float* __restrict__ W2r) {
    int i = blockIdx.x * blockDim.x + threadIdx.x;
    if (i >= 256 * 256) return;
    int k = i >> 8, t = i & 255;
    g_WT1[i] = (k < 128) ? W1l[t * 128 + k] : W1r[t * 128 + (k - 128)];
    g_WT2[i] = (t < 128) ? W2l[t * 256 + k] : W2r[(t - 128) * 256 + k];
}

// ---- edge scatter: one warp per edge, 128 floats; LDG.128 gather + 4x scalar RED ----
// edge_index is int32 (JAX x64 disabled downcasts the int64 request).
template <int PHASE>
__global__ void scatter_kernel(const float4* __restrict__ xin,
                               const int* __restrict__ ei, int E) {
    int w = (blockIdx.x * blockDim.x + threadIdx.x) >> 5;
    int lane = threadIdx.x & 31;
    if (w >= E) return;
    int s = ei[w];
    int d = ei[E + w];
    const float4* feat = PHASE ? (const float4*)g_p : xin;
    float4 v = feat[s * 32 + lane];
    float* dst = (float*)((PHASE ? g_aggp : g_agg1) + d * 32 + lane);
    atomicAdd(dst + 0, v.x);
    atomicAdd(dst + 1, v.y);
    atomicAdd(dst + 2, v.z);
    atomicAdd(dst + 3, v.w);
    if (PHASE == 0 && lane == 0) atomicAdd(g_deg + d, 1.0f);
}

// ---- fused dense kernel: h = relu([mean1 || x] @ WT1 + b1) (SMEM only),
//      then [p || r2] = h @ WT2.  32 nodes / block, 8 nodes x 4 outs / thread. ----
__global__ __launch_bounds__(256, 2) void gemm_fused(const float4* __restrict__ x,
                                                     const float* __restrict__ b1) {
    __shared__ __align__(16) float s_in[32 * 256];
    int tid = threadIdx.x;
    int node0 = blockIdx.x * 32;
    int oc = tid & 63;   // float4 output column (t4 = oc*4)
    int ng = tid >> 6;   // node group 0..3

    // Stage A: stage [mean1 || x] for 32 nodes into SMEM
    for (int i = tid; i < 2048; i += 256) {
        int n = i >> 6;
        int c = i & 63;
        int node = node0 + n;
        if (node >= N_NODES) node = N_NODES - 1;
        float4 v;
        if (c < 32) {
            float invd = 1.0f / fmaxf(g_deg[node], 1.0f);
            v = g_agg1[node * 32 + c];
            v.x *= invd; v.y *= invd; v.z *= invd; v.w *= invd;
        } else {
            v = x[node * 32 + (c - 32)];
        }
        ((float4*)s_in)[i] = v;
    }
    __syncthreads();

    float acc[8][4];
#pragma unroll
    for (int j = 0; j < 8; j++)
#pragma unroll
        for (int c = 0; c < 4; c++) acc[j][c] = 0.f;

    // Stage B: layer-1 GEMM
    const float4* wt1 = (const float4*)g_WT1;
#pragma unroll 2
    for (int k = 0; k < 256; k++) {
        float4 w = wt1[k * 64 + oc];
        float sv[8];
#pragma unroll
        for (int j = 0; j < 8; j++) sv[j] = s_in[(ng * 8 + j) * 256 + k];
#pragma unroll
        for (int j = 0; j < 8; j++) {
            acc[j][0] += sv[j] * w.x;
            acc[j][1] += sv[j] * w.y;
            acc[j][2] += sv[j] * w.z;
            acc[j][3] += sv[j] * w.w;
        }
    }

    // bias + relu, write h back to SMEM (never to global)
    float4 bb = ((const float4*)b1)[oc];
    __syncthreads();
#pragma unroll
    for (int j = 0; j < 8; j++) {
        float4 hv;
        hv.x = fmaxf(acc[j][0] + bb.x, 0.f);
        hv.y = fmaxf(acc[j][1] + bb.y, 0.f);
        hv.z = fmaxf(acc[j][2] + bb.z, 0.f);
        hv.w = fmaxf(acc[j][3] + bb.w, 0.f);
        ((float4*)s_in)[(ng * 8 + j) * 64 + oc] = hv;
        acc[j][0] = acc[j][1] = acc[j][2] = acc[j][3] = 0.f;
    }
    __syncthreads();

    // Stage C: layer-2 projections p = h@W2_l.T, r2 = h@W2_r.T
    const float4* wt2 = (const float4*)g_WT2;
#pragma unroll 2
    for (int k = 0; k < 256; k++) {
        float4 w = wt2[k * 64 + oc];
        float sv[8];
#pragma unroll
        for (int j = 0; j < 8; j++) sv[j] = s_in[(ng * 8 + j) * 256 + k];
#pragma unroll
        for (int j = 0; j < 8; j++) {
            acc[j][0] += sv[j] * w.x;
            acc[j][1] += sv[j] * w.y;
            acc[j][2] += sv[j] * w.z;
            acc[j][3] += sv[j] * w.w;
        }
    }

#pragma unroll
    for (int j = 0; j < 8; j++) {
        int node = node0 + ng * 8 + j;
        if (node < N_NODES) {
            float4 o = make_float4(acc[j][0], acc[j][1], acc[j][2], acc[j][3]);
            if (oc < 32) g_p[node * 32 + oc] = o;
            else         g_r2[node * 32 + (oc - 32)] = o;
        }
    }
}

// ---- epilogue: out = agg_p/deg + b2 + r2 ----
__global__ void final_kernel(const float* __restrict__ b2, float4* __restrict__ out) {
    int i = blockIdx.x * blockDim.x + threadIdx.x;
    if (i >= N_NODES * 32) return;
    int node = i >> 5, c = i & 31;
    float invd = 1.0f / fmaxf(g_deg[node], 1.0f);
    float4 a = g_aggp[i];
    float4 r = g_r2[i];
    float4 bb = ((const float4*)b2)[c];
    float4 o;
    o.x = a.x * invd + bb.x + r.x;
    o.y = a.y * invd + bb.y + r.y;
    o.z = a.z * invd + bb.z + r.z;
    o.w = a.w * invd + bb.w + r.w;
    out[i] = o;
}

extern "C" void kernel_launch(void* const* d_in, const int* in_sizes, int n_in,
                              void* d_out, int out_size) {
    const float4* x   = (const float4*)d_in[0];
    const int*    ei  = (const int*)d_in[1];
    const float*  W1l = (const float*)d_in[2];
    const float*  b1  = (const float*)d_in[3];
    const float*  W1r = (const float*)d_in[4];
    const float*  W2l = (const float*)d_in[5];
    const float*  b2  = (const float*)d_in[6];
    const float*  W2r = (const float*)d_in[7];
    int E = in_sizes[1] / 2;

    zero_kernel<<<(N_NODES * 32 + 255) / 256, 256>>>();
    prep_weights<<<(256 * 256 + 255) / 256, 256>>>(W1l, W1r, W2l, W2r);
    scatter_kernel<0><<<(E + 7) / 8, 256>>>(x, ei, E);
    gemm_fused<<<(N_NODES + 31) / 32, 256>>>(x, b1);
    scatter_kernel<1><<<(E + 7) / 8, 256>>>(x, ei, E);
    final_kernel<<<(N_NODES * 32 + 255) / 256, 256>>>(b2, (float4*)d_out);
}

// round 5
// speedup vs baseline: 1.2887x; 1.2887x over previous
#include <cuda_runtime.h>
#include <cstdint>

#define N_NODES 50000

// ---- scratch (static __device__ — no allocations allowed) ----
__device__ __align__(16) float4 g_agg1[N_NODES * 32];   // [N,128] sum of x[src] per dst
__device__ __align__(16) float4 g_aggp[N_NODES * 32];   // [N,128] sum of p[src] per dst
__device__ __align__(16) float4 g_p   [N_NODES * 32];   // h @ W2_l.T
__device__ __align__(16) float4 g_r2  [N_NODES * 32];   // h @ W2_r.T
__device__ float  g_deg [N_NODES];
__device__ __align__(16) float g_WT1 [256 * 256];  // [k][t] tf32-rounded; k<128 -> W1_l else W1_r
__device__ __align__(16) float g_WT2 [256 * 256];  // [k][j] tf32-rounded; j<128 -> W2_l else W2_r

__device__ __forceinline__ float to_tf32(float v) {
    asm("cvt.rna.tf32.f32 %0, %1;" : "=f"(v) : "f"(v));
    return v;
}

// ---- zero the accumulators ----
__global__ void zero_kernel() {
    int i = blockIdx.x * blockDim.x + threadIdx.x;
    float4 z = make_float4(0.f, 0.f, 0.f, 0.f);
    if (i < N_NODES * 32) { g_agg1[i] = z; g_aggp[i] = z; }
    if (i < N_NODES) g_deg[i] = 0.f;
}

// ---- transpose/pack weights (tf32-rounded) for the MMA ----
__global__ void prep_weights(const float* __restrict__ W1l, const float* __restrict__ W1r,
                             const float* __restrict__ W2l, const float* __restrict__ W2r) {
    int i = blockIdx.x * blockDim.x + threadIdx.x;
    if (i >= 256 * 256) return;
    int k = i >> 8, t = i & 255;
    g_WT1[i] = to_tf32((k < 128) ? W1l[t * 128 + k] : W1r[t * 128 + (k - 128)]);
    g_WT2[i] = to_tf32((t < 128) ? W2l[t * 256 + k] : W2r[(t - 128) * 256 + k]);
}

// ---- edge scatter: one warp per edge, 128 floats; LDG.128 gather + 4x scalar RED ----
template <int PHASE>
__global__ void scatter_kernel(const float4* __restrict__ xin,
                               const int* __restrict__ ei, int E) {
    int w = (blockIdx.x * blockDim.x + threadIdx.x) >> 5;
    int lane = threadIdx.x & 31;
    if (w >= E) return;
    int s = ei[w];
    int d = ei[E + w];
    const float4* feat = PHASE ? (const float4*)g_p : xin;
    float4 v = feat[s * 32 + lane];
    float* dst = (float*)((PHASE ? g_aggp : g_agg1) + d * 32 + lane);
    atomicAdd(dst + 0, v.x);
    atomicAdd(dst + 1, v.y);
    atomicAdd(dst + 2, v.z);
    atomicAdd(dst + 3, v.w);
    if (PHASE == 0 && lane == 0) atomicAdd(g_deg + d, 1.0f);
}

// ================= TF32 tensor-core fused double-GEMM =================
// Per CTA: 64 nodes, 256 outs. 8 warps, each warp a 64x32 output tile.
#define SA_STR 260
#define SW_STR 264
#define SA_FLOATS (64 * SA_STR)
#define SWBUF_FLOATS (32 * SW_STR)
#define SMEM_FLOATS (SA_FLOATS + 2 * SWBUF_FLOATS + SA_FLOATS)

__device__ __forceinline__ void cp16(float* dst, const float* src) {
    uint32_t sa = (uint32_t)__cvta_generic_to_shared(dst);
    asm volatile("cp.async.ca.shared.global [%0], [%1], 16;" :: "r"(sa), "l"(src));
}
__device__ __forceinline__ void cp_commit() { asm volatile("cp.async.commit_group;"); }
__device__ __forceinline__ void cp_wait0()  { asm volatile("cp.async.wait_group 0;"); }

// copy one 32x256 weight chunk (kc) into a SW buffer
__device__ __forceinline__ void load_chunk(float* buf, const float* Wg, int kc, int tid) {
#pragma unroll
    for (int i = 0; i < 8; i++) {
        int idx = tid + i * 256;          // f4 index over 32x64
        int r = idx >> 6, c4 = idx & 63;
        cp16(buf + r * SW_STR + c4 * 4, Wg + (kc * 32 + r) * 256 + c4 * 4);
    }
}

__device__ __forceinline__ void mma_tf32(float* d, const uint32_t* a, const uint32_t* b) {
    asm volatile(
        "mma.sync.aligned.m16n8k8.row.col.f32.tf32.tf32.f32 "
        "{%0,%1,%2,%3}, {%4,%5,%6,%7}, {%8,%9}, {%0,%1,%2,%3};"
        : "+f"(d[0]), "+f"(d[1]), "+f"(d[2]), "+f"(d[3])
        : "r"(a[0]), "r"(a[1]), "r"(a[2]), "r"(a[3]), "r"(b[0]), "r"(b[1]));
}

// one 256-K GEMM: acc[mt][nt][4] += A(64x256, smem) @ W(256x256, global via sW)
__device__ __forceinline__ void gemm_k256(const float* __restrict__ A, const float* __restrict__ Wg,
                                          float* sW0, float* sW1,
                                          float acc[4][4][4], int tid, int lane, int n_base) {
    float* sw[2] = {sW0, sW1};
    for (int kc = 0; kc < 8; kc++) {
        cp_wait0();
        __syncthreads();
        if (kc < 7) { load_chunk(sw[(kc + 1) & 1], Wg, kc + 1, tid); cp_commit(); }
        const float* Wc = sw[kc & 1];
#pragma unroll
        for (int k8 = 0; k8 < 4; k8++) {
            int k0 = kc * 32 + k8 * 8;
            uint32_t af[4][4];
#pragma unroll
            for (int mt = 0; mt < 4; mt++) {
                const float* Ar = A + (mt * 16 + (lane >> 2)) * SA_STR + k0 + (lane & 3);
                // PTX m16n8k8.tf32 A fragment: a0=(g,t) a1=(g+8,t) a2=(g,t+4) a3=(g+8,t+4)
                af[mt][0] = __float_as_uint(Ar[0]);
                af[mt][1] = __float_as_uint(Ar[8 * SA_STR]);
                af[mt][2] = __float_as_uint(Ar[4]);
                af[mt][3] = __float_as_uint(Ar[8 * SA_STR + 4]);
            }
            uint32_t bf[4][2];
#pragma unroll
            for (int nt = 0; nt < 4; nt++) {
                const float* Br = Wc + (k8 * 8 + (lane & 3)) * SW_STR + n_base + nt * 8 + (lane >> 2);
                bf[nt][0] = __float_as_uint(Br[0]);
                bf[nt][1] = __float_as_uint(Br[4 * SW_STR]);
            }
#pragma unroll
            for (int mt = 0; mt < 4; mt++)
#pragma unroll
                for (int nt = 0; nt < 4; nt++)
                    mma_tf32(acc[mt][nt], af[mt], bf[nt]);
        }
    }
}

__global__ __launch_bounds__(256, 1) void gemm_mma(const float4* __restrict__ x,
                                                   const float* __restrict__ b1) {
    extern __shared__ float smem[];
    float* sA  = smem;
    float* sW0 = smem + SA_FLOATS;
    float* sW1 = sW0 + SWBUF_FLOATS;
    float* sH  = sW1 + SWBUF_FLOATS;

    int tid = threadIdx.x, lane = tid & 31, warp = tid >> 5;
    int node0 = blockIdx.x * 64;
    int n_base = warp * 32;

    // prologue: start W1 chunk 0
    load_chunk(sW0, g_WT1, 0, tid);
    cp_commit();

    // stage A = [mean1 || x] for 64 nodes (tf32-rounded)
#pragma unroll
    for (int i = tid; i < 64 * 64; i += 256) {
        int n = i >> 6, c = i & 63;
        int node = node0 + n;
        if (node >= N_NODES) node = N_NODES - 1;
        float4 v;
        if (c < 32) {
            float invd = 1.0f / fmaxf(g_deg[node], 1.0f);
            v = g_agg1[node * 32 + c];
            v.x *= invd; v.y *= invd; v.z *= invd; v.w *= invd;
        } else {
            v = x[node * 32 + (c - 32)];
        }
        float* d = sA + n * SA_STR + c * 4;
        d[0] = to_tf32(v.x); d[1] = to_tf32(v.y); d[2] = to_tf32(v.z); d[3] = to_tf32(v.w);
    }

    float acc[4][4][4];
#pragma unroll
    for (int a = 0; a < 4; a++)
#pragma unroll
        for (int b = 0; b < 4; b++)
#pragma unroll
            for (int c = 0; c < 4; c++) acc[a][b][c] = 0.f;

    // ---- GEMM1: h = relu(A @ WT1 + b1) ----
    gemm_k256(sA, g_WT1, sW0, sW1, acc, tid, lane, n_base);

    // start W2 chunk 0 (overlaps epilogue)
    load_chunk(sW0, g_WT2, 0, tid);
    cp_commit();

    // epilogue 1: bias + relu -> sH (tf32)
#pragma unroll
    for (int mt = 0; mt < 4; mt++) {
        int row = mt * 16 + (lane >> 2);
#pragma unroll
        for (int nt = 0; nt < 4; nt++) {
            int col = n_base + nt * 8 + (lane & 3) * 2;
            float bb0 = __ldg(b1 + col), bb1 = __ldg(b1 + col + 1);
            sH[row * SA_STR + col]           = to_tf32(fmaxf(acc[mt][nt][0] + bb0, 0.f));
            sH[row * SA_STR + col + 1]       = to_tf32(fmaxf(acc[mt][nt][1] + bb1, 0.f));
            sH[(row + 8) * SA_STR + col]     = to_tf32(fmaxf(acc[mt][nt][2] + bb0, 0.f));
            sH[(row + 8) * SA_STR + col + 1] = to_tf32(fmaxf(acc[mt][nt][3] + bb1, 0.f));
            acc[mt][nt][0] = acc[mt][nt][1] = acc[mt][nt][2] = acc[mt][nt][3] = 0.f;
        }
    }

    // ---- GEMM2: [p || r2] = h @ WT2 ----  (first wait+sync also fences sH)
    gemm_k256(sH, g_WT2, sW0, sW1, acc, tid, lane, n_base);

    // store p (cols 0..127) / r2 (cols 128..255)
    float* gp = (float*)g_p;
    float* gr = (float*)g_r2;
#pragma unroll
    for (int mt = 0; mt < 4; mt++) {
        int row = mt * 16 + (lane >> 2);
#pragma unroll
        for (int nt = 0; nt < 4; nt++) {
            int col = n_base + nt * 8 + (lane & 3) * 2;
            float* base = (col < 128) ? gp : gr;
            int cc = col & 127;
            int node = node0 + row;
            if (node < N_NODES) {
                float2 v0 = make_float2(acc[mt][nt][0], acc[mt][nt][1]);
                *(float2*)(base + node * 128 + cc) = v0;
            }
            if (node + 8 < N_NODES) {
                float2 v1 = make_float2(acc[mt][nt][2], acc[mt][nt][3]);
                *(float2*)(base + (node + 8) * 128 + cc) = v1;
            }
        }
    }
}

// ---- epilogue: out = agg_p/deg + b2 + r2 ----
__global__ void final_kernel(const float* __restrict__ b2, float4* __restrict__ out) {
    int i = blockIdx.x * blockDim.x + threadIdx.x;
    if (i >= N_NODES * 32) return;
    int node = i >> 5, c = i & 31;
    float invd = 1.0f / fmaxf(g_deg[node], 1.0f);
    float4 a = g_aggp[i];
    float4 r = g_r2[i];
    float4 bb = ((const float4*)b2)[c];
    float4 o;
    o.x = a.x * invd + bb.x + r.x;
    o.y = a.y * invd + bb.y + r.y;
    o.z = a.z * invd + bb.z + r.z;
    o.w = a.w * invd + bb.w + r.w;
    out[i] = o;
}

extern "C" void kernel_launch(void* const* d_in, const int* in_sizes, int n_in,
                              void* d_out, int out_size) {
    const float4* x   = (const float4*)d_in[0];
    const int*    ei  = (const int*)d_in[1];
    const float*  W1l = (const float*)d_in[2];
    const float*  b1  = (const float*)d_in[3];
    const float*  W1r = (const float*)d_in[4];
    const float*  W2l = (const float*)d_in[5];
    const float*  b2  = (const float*)d_in[6];
    const float*  W2r = (const float*)d_in[7];
    int E = in_sizes[1] / 2;

    cudaFuncSetAttribute(gemm_mma, cudaFuncAttributeMaxDynamicSharedMemorySize,
                         SMEM_FLOATS * 4);

    zero_kernel<<<(N_NODES * 32 + 255) / 256, 256>>>();
    prep_weights<<<(256 * 256 + 255) / 256, 256>>>(W1l, W1r, W2l, W2r);
    scatter_kernel<0><<<(E + 7) / 8, 256>>>(x, ei, E);
    gemm_mma<<<(N_NODES + 63) / 64, 256, SMEM_FLOATS * 4>>>(x, b1);
    scatter_kernel<1><<<(E + 7) / 8, 256>>>(x, ei, E);
    final_kernel<<<(N_NODES * 32 + 255) / 256, 256>>>(b2, (float4*)d_out);
}

// round 6
// speedup vs baseline: 2.7993x; 2.1722x over previous
#include <cuda_runtime.h>
#include <cstdint>

#define N_NODES 50000
#define E_MAX   800000

// ---- scratch (static __device__ — no allocations allowed) ----
__device__ __align__(16) float4 g_agg1[N_NODES * 32];   // [N,128] MEAN of x[src] per dst
__device__ __align__(16) float4 g_p   [N_NODES * 32];   // h @ W2_l.T
__device__ __align__(16) float4 g_r2  [N_NODES * 32];   // h @ W2_r.T
__device__ __align__(16) float g_WT1 [256 * 256];  // [k][t] tf32; k<128 -> W1_l else W1_r
__device__ __align__(16) float g_WT2 [256 * 256];  // [k][j] tf32; j<128 -> W2_l else W2_r
// CSR by dst
__device__ int g_cnt [N_NODES];
__device__ int g_fill[N_NODES];
__device__ int g_rowptr[N_NODES + 1];
__device__ int g_eidx[E_MAX];

__device__ __forceinline__ float to_tf32(float v) {
    asm("cvt.rna.tf32.f32 %0, %1;" : "=f"(v) : "f"(v));
    return v;
}

// ================= CSR build =================
__global__ void zero_cnt() {
    int i = blockIdx.x * blockDim.x + threadIdx.x;
    if (i < N_NODES) g_cnt[i] = 0;
}
__global__ void hist_kernel(const int* __restrict__ ei, int E) {
    int e = blockIdx.x * blockDim.x + threadIdx.x;
    if (e < E) atomicAdd(&g_cnt[ei[E + e]], 1);
}
__global__ void scan_rowptr(int E) {
    __shared__ int part[1024];
    const int CH = (N_NODES + 1023) / 1024;   // 49
    int t = threadIdx.x;
    int begin = t * CH, end = min(begin + CH, N_NODES);
    int s = 0;
    for (int i = begin; i < end; i++) s += g_cnt[i];
    part[t] = s;
    __syncthreads();
    for (int off = 1; off < 1024; off <<= 1) {
        int add = (t >= off) ? part[t - off] : 0;
        __syncthreads();
        part[t] += add;
        __syncthreads();
    }
    int run = part[t] - s;   // exclusive prefix for this chunk
    for (int i = begin; i < end; i++) {
        g_rowptr[i] = run;
        g_fill[i] = run;
        run += g_cnt[i];
    }
    if (t == 1023) g_rowptr[N_NODES] = E;
}
__global__ void fill_kernel(const int* __restrict__ ei, int E) {
    int e = blockIdx.x * blockDim.x + threadIdx.x;
    if (e >= E) return;
    int s = ei[e];
    int d = ei[E + e];
    int pos = atomicAdd(&g_fill[d], 1);
    g_eidx[pos] = s;
}

// ================= gather-side aggregation (no float atomics) =================
// one warp per node; lane owns one float4 of the 128-float feature.
__device__ __forceinline__ float4 agg_row(const float4* __restrict__ feat,
                                          int row, int end, int lane) {
    float4 acc = make_float4(0.f, 0.f, 0.f, 0.f);
    int j = row;
    for (; j + 4 <= end; j += 4) {
        int s0 = __ldg(g_eidx + j), s1 = __ldg(g_eidx + j + 1);
        int s2 = __ldg(g_eidx + j + 2), s3 = __ldg(g_eidx + j + 3);
        float4 v0 = feat[s0 * 32 + lane];
        float4 v1 = feat[s1 * 32 + lane];
        float4 v2 = feat[s2 * 32 + lane];
        float4 v3 = feat[s3 * 32 + lane];
        acc.x += v0.x + v1.x + v2.x + v3.x;
        acc.y += v0.y + v1.y + v2.y + v3.y;
        acc.z += v0.z + v1.z + v2.z + v3.z;
        acc.w += v0.w + v1.w + v2.w + v3.w;
    }
    for (; j < end; j++) {
        int s = __ldg(g_eidx + j);
        float4 v = feat[s * 32 + lane];
        acc.x += v.x; acc.y += v.y; acc.z += v.z; acc.w += v.w;
    }
    return acc;
}

__global__ void agg_mean_x(const float4* __restrict__ x) {
    int node = blockIdx.x * 8 + (threadIdx.x >> 5);
    int lane = threadIdx.x & 31;
    if (node >= N_NODES) return;
    int row = g_rowptr[node], end = g_rowptr[node + 1];
    float4 acc = agg_row(x, row, end, lane);
    float invd = 1.0f / fmaxf((float)(end - row), 1.0f);
    acc.x *= invd; acc.y *= invd; acc.z *= invd; acc.w *= invd;
    g_agg1[node * 32 + lane] = acc;
}

// out = mean(p over nbrs) + b2 + r2
__global__ void agg_final(const float* __restrict__ b2, float4* __restrict__ out) {
    int node = blockIdx.x * 8 + (threadIdx.x >> 5);
    int lane = threadIdx.x & 31;
    if (node >= N_NODES) return;
    int row = g_rowptr[node], end = g_rowptr[node + 1];
    float4 acc = agg_row((const float4*)g_p, row, end, lane);
    float invd = 1.0f / fmaxf((float)(end - row), 1.0f);
    float4 r = g_r2[node * 32 + lane];
    float4 bb = ((const float4*)b2)[lane];
    float4 o;
    o.x = acc.x * invd + bb.x + r.x;
    o.y = acc.y * invd + bb.y + r.y;
    o.z = acc.z * invd + bb.z + r.z;
    o.w = acc.w * invd + bb.w + r.w;
    out[node * 32 + lane] = o;
}

// ---- transpose/pack weights (tf32-rounded) for the MMA ----
__global__ void prep_weights(const float* __restrict__ W1l, const float* __restrict__ W1r,
                             const float* __restrict__ W2l, const float* __restrict__ W2r) {
    int i = blockIdx.x * blockDim.x + threadIdx.x;
    if (i >= 256 * 256) return;
    int k = i >> 8, t = i & 255;
    g_WT1[i] = to_tf32((k < 128) ? W1l[t * 128 + k] : W1r[t * 128 + (k - 128)]);
    g_WT2[i] = to_tf32((t < 128) ? W2l[t * 256 + k] : W2r[(t - 128) * 256 + k]);
}

// ================= TF32 tensor-core fused double-GEMM =================
#define SA_STR 260
#define SW_STR 264
#define SA_FLOATS (64 * SA_STR)
#define SWBUF_FLOATS (32 * SW_STR)
#define SMEM_FLOATS (SA_FLOATS + 2 * SWBUF_FLOATS + SA_FLOATS)

__device__ __forceinline__ void cp16(float* dst, const float* src) {
    uint32_t sa = (uint32_t)__cvta_generic_to_shared(dst);
    asm volatile("cp.async.ca.shared.global [%0], [%1], 16;" :: "r"(sa), "l"(src));
}
__device__ __forceinline__ void cp_commit() { asm volatile("cp.async.commit_group;"); }
__device__ __forceinline__ void cp_wait0()  { asm volatile("cp.async.wait_group 0;"); }

__device__ __forceinline__ void load_chunk(float* buf, const float* Wg, int kc, int tid) {
#pragma unroll
    for (int i = 0; i < 8; i++) {
        int idx = tid + i * 256;
        int r = idx >> 6, c4 = idx & 63;
        cp16(buf + r * SW_STR + c4 * 4, Wg + (kc * 32 + r) * 256 + c4 * 4);
    }
}

__device__ __forceinline__ void mma_tf32(float* d, const uint32_t* a, const uint32_t* b) {
    asm volatile(
        "mma.sync.aligned.m16n8k8.row.col.f32.tf32.tf32.f32 "
        "{%0,%1,%2,%3}, {%4,%5,%6,%7}, {%8,%9}, {%0,%1,%2,%3};"
        : "+f"(d[0]), "+f"(d[1]), "+f"(d[2]), "+f"(d[3])
        : "r"(a[0]), "r"(a[1]), "r"(a[2]), "r"(a[3]), "r"(b[0]), "r"(b[1]));
}

__device__ __forceinline__ void gemm_k256(const float* __restrict__ A, const float* __restrict__ Wg,
                                          float* sW0, float* sW1,
                                          float acc[4][4][4], int tid, int lane, int n_base) {
    float* sw[2] = {sW0, sW1};
    for (int kc = 0; kc < 8; kc++) {
        cp_wait0();
        __syncthreads();
        if (kc < 7) { load_chunk(sw[(kc + 1) & 1], Wg, kc + 1, tid); cp_commit(); }
        const float* Wc = sw[kc & 1];
#pragma unroll
        for (int k8 = 0; k8 < 4; k8++) {
            int k0 = kc * 32 + k8 * 8;
            uint32_t af[4][4];
#pragma unroll
            for (int mt = 0; mt < 4; mt++) {
                const float* Ar = A + (mt * 16 + (lane >> 2)) * SA_STR + k0 + (lane & 3);
                af[mt][0] = __float_as_uint(Ar[0]);
                af[mt][1] = __float_as_uint(Ar[8 * SA_STR]);
                af[mt][2] = __float_as_uint(Ar[4]);
                af[mt][3] = __float_as_uint(Ar[8 * SA_STR + 4]);
            }
            uint32_t bf[4][2];
#pragma unroll
            for (int nt = 0; nt < 4; nt++) {
                const float* Br = Wc + (k8 * 8 + (lane & 3)) * SW_STR + n_base + nt * 8 + (lane >> 2);
                bf[nt][0] = __float_as_uint(Br[0]);
                bf[nt][1] = __float_as_uint(Br[4 * SW_STR]);
            }
#pragma unroll
            for (int mt = 0; mt < 4; mt++)
#pragma unroll
                for (int nt = 0; nt < 4; nt++)
                    mma_tf32(acc[mt][nt], af[mt], bf[nt]);
        }
    }
}

__global__ __launch_bounds__(256, 1) void gemm_mma(const float4* __restrict__ x,
                                                   const float* __restrict__ b1) {
    extern __shared__ float smem[];
    float* sA  = smem;
    float* sW0 = smem + SA_FLOATS;
    float* sW1 = sW0 + SWBUF_FLOATS;
    float* sH  = sW1 + SWBUF_FLOATS;

    int tid = threadIdx.x, lane = tid & 31, warp = tid >> 5;
    int node0 = blockIdx.x * 64;
    int n_base = warp * 32;

    load_chunk(sW0, g_WT1, 0, tid);
    cp_commit();

    // stage A = [mean1 || x] (g_agg1 is already the mean)
#pragma unroll
    for (int i = tid; i < 64 * 64; i += 256) {
        int n = i >> 6, c = i & 63;
        int node = node0 + n;
        if (node >= N_NODES) node = N_NODES - 1;
        float4 v = (c < 32) ? g_agg1[node * 32 + c] : x[node * 32 + (c - 32)];
        float* d = sA + n * SA_STR + c * 4;
        d[0] = to_tf32(v.x); d[1] = to_tf32(v.y); d[2] = to_tf32(v.z); d[3] = to_tf32(v.w);
    }

    float acc[4][4][4];
#pragma unroll
    for (int a = 0; a < 4; a++)
#pragma unroll
        for (int b = 0; b < 4; b++)
#pragma unroll
            for (int c = 0; c < 4; c++) acc[a][b][c] = 0.f;

    gemm_k256(sA, g_WT1, sW0, sW1, acc, tid, lane, n_base);

    load_chunk(sW0, g_WT2, 0, tid);
    cp_commit();

#pragma unroll
    for (int mt = 0; mt < 4; mt++) {
        int row = mt * 16 + (lane >> 2);
#pragma unroll
        for (int nt = 0; nt < 4; nt++) {
            int col = n_base + nt * 8 + (lane & 3) * 2;
            float bb0 = __ldg(b1 + col), bb1 = __ldg(b1 + col + 1);
            sH[row * SA_STR + col]           = to_tf32(fmaxf(acc[mt][nt][0] + bb0, 0.f));
            sH[row * SA_STR + col + 1]       = to_tf32(fmaxf(acc[mt][nt][1] + bb1, 0.f));
            sH[(row + 8) * SA_STR + col]     = to_tf32(fmaxf(acc[mt][nt][2] + bb0, 0.f));
            sH[(row + 8) * SA_STR + col + 1] = to_tf32(fmaxf(acc[mt][nt][3] + bb1, 0.f));
            acc[mt][nt][0] = acc[mt][nt][1] = acc[mt][nt][2] = acc[mt][nt][3] = 0.f;
        }
    }

    gemm_k256(sH, g_WT2, sW0, sW1, acc, tid, lane, n_base);

    float* gp = (float*)g_p;
    float* gr = (float*)g_r2;
#pragma unroll
    for (int mt = 0; mt < 4; mt++) {
        int row = mt * 16 + (lane >> 2);
#pragma unroll
        for (int nt = 0; nt < 4; nt++) {
            int col = n_base + nt * 8 + (lane & 3) * 2;
            float* base = (col < 128) ? gp : gr;
            int cc = col & 127;
            int node = node0 + row;
            if (node < N_NODES)
                *(float2*)(base + node * 128 + cc) = make_float2(acc[mt][nt][0], acc[mt][nt][1]);
            if (node + 8 < N_NODES)
                *(float2*)(base + (node + 8) * 128 + cc) = make_float2(acc[mt][nt][2], acc[mt][nt][3]);
        }
    }
}

extern "C" void kernel_launch(void* const* d_in, const int* in_sizes, int n_in,
                              void* d_out, int out_size) {
    const float4* x   = (const float4*)d_in[0];
    const int*    ei  = (const int*)d_in[1];
    const float*  W1l = (const float*)d_in[2];
    const float*  b1  = (const float*)d_in[3];
    const float*  W1r = (const float*)d_in[4];
    const float*  W2l = (const float*)d_in[5];
    const float*  b2  = (const float*)d_in[6];
    const float*  W2r = (const float*)d_in[7];
    int E = in_sizes[1] / 2;

    cudaFuncSetAttribute(gemm_mma, cudaFuncAttributeMaxDynamicSharedMemorySize,
                         SMEM_FLOATS * 4);

    zero_cnt<<<(N_NODES + 255) / 256, 256>>>();
    hist_kernel<<<(E + 255) / 256, 256>>>(ei, E);
    scan_rowptr<<<1, 1024>>>(E);
    fill_kernel<<<(E + 255) / 256, 256>>>(ei, E);
    prep_weights<<<(256 * 256 + 255) / 256, 256>>>(W1l, W1r, W2l, W2r);
    agg_mean_x<<<(N_NODES + 7) / 8, 256>>>(x);
    gemm_mma<<<(N_NODES + 63) / 64, 256, SMEM_FLOATS * 4>>>(x, b1);
    agg_final<<<(N_NODES + 7) / 8, 256>>>(b2, (float4*)d_out);
}

// round 7
// speedup vs baseline: 3.7291x; 1.3322x over previous
#include <cuda_runtime.h>
#include <cuda_fp16.h>
#include <cstdint>

#define N_NODES 50000
#define E_MAX   800000

// ---- scratch (static __device__ — no allocations allowed) ----
__device__ __align__(16) float4 g_agg1[N_NODES * 32];   // [N,128] MEAN of x[src] per dst (fp32)
__device__ __align__(16) __half g_ph [N_NODES * 128];   // h @ W2_l.T  (fp16)
__device__ __align__(16) float4 g_r2 [N_NODES * 32];    // h @ W2_r.T  (fp32)
__device__ __align__(16) __half g_W1h[256 * 256];       // [t][k] fp16; k<128 -> W1_l else W1_r
__device__ __align__(16) __half g_W2h[256 * 256];       // [j][k] fp16; j<128 -> W2_l else W2_r
// CSR by dst
__device__ int g_cnt [N_NODES];
__device__ int g_fill[N_NODES];
__device__ int g_rowptr[N_NODES + 1];
__device__ int g_eidx[E_MAX];

// ================= CSR build =================
__global__ void zero_cnt() {
    int i = blockIdx.x * blockDim.x + threadIdx.x;
    if (i < N_NODES) g_cnt[i] = 0;
}
__global__ void hist_kernel(const int* __restrict__ ei, int E) {
    int e = blockIdx.x * blockDim.x + threadIdx.x;
    if (e < E) atomicAdd(&g_cnt[ei[E + e]], 1);
}
__global__ void scan_rowptr(int E) {
    __shared__ int part[1024];
    const int CH = (N_NODES + 1023) / 1024;
    int t = threadIdx.x;
    int begin = t * CH, end = min(begin + CH, N_NODES);
    int s = 0;
    for (int i = begin; i < end; i++) s += g_cnt[i];
    part[t] = s;
    __syncthreads();
    for (int off = 1; off < 1024; off <<= 1) {
        int add = (t >= off) ? part[t - off] : 0;
        __syncthreads();
        part[t] += add;
        __syncthreads();
    }
    int run = part[t] - s;
    for (int i = begin; i < end; i++) {
        g_rowptr[i] = run;
        g_fill[i] = run;
        run += g_cnt[i];
    }
    if (t == 1023) g_rowptr[N_NODES] = E;
}
__global__ void fill_kernel(const int* __restrict__ ei, int E) {
    int e = blockIdx.x * blockDim.x + threadIdx.x;
    if (e >= E) return;
    int s = ei[e];
    int d = ei[E + e];
    int pos = atomicAdd(&g_fill[d], 1);
    g_eidx[pos] = s;
}

// ================= gather-side aggregation (no float atomics) =================
__global__ void agg_mean_x(const float4* __restrict__ x) {
    int node = blockIdx.x * 8 + (threadIdx.x >> 5);
    int lane = threadIdx.x & 31;
    if (node >= N_NODES) return;
    int row = g_rowptr[node], end = g_rowptr[node + 1];
    float4 acc = make_float4(0.f, 0.f, 0.f, 0.f);
    int j = row;
    for (; j + 4 <= end; j += 4) {
        int s0 = __ldg(g_eidx + j), s1 = __ldg(g_eidx + j + 1);
        int s2 = __ldg(g_eidx + j + 2), s3 = __ldg(g_eidx + j + 3);
        float4 v0 = x[s0 * 32 + lane], v1 = x[s1 * 32 + lane];
        float4 v2 = x[s2 * 32 + lane], v3 = x[s3 * 32 + lane];
        acc.x += v0.x + v1.x + v2.x + v3.x;
        acc.y += v0.y + v1.y + v2.y + v3.y;
        acc.z += v0.z + v1.z + v2.z + v3.z;
        acc.w += v0.w + v1.w + v2.w + v3.w;
    }
    for (; j < end; j++) {
        int s = __ldg(g_eidx + j);
        float4 v = x[s * 32 + lane];
        acc.x += v.x; acc.y += v.y; acc.z += v.z; acc.w += v.w;
    }
    float invd = 1.0f / fmaxf((float)(end - row), 1.0f);
    acc.x *= invd; acc.y *= invd; acc.z *= invd; acc.w *= invd;
    g_agg1[node * 32 + lane] = acc;
}

// out = mean(p over nbrs) + b2 + r2    (p is fp16, 8B per lane)
__global__ void agg_final(const float* __restrict__ b2, float4* __restrict__ out) {
    int node = blockIdx.x * 8 + (threadIdx.x >> 5);
    int lane = threadIdx.x & 31;
    if (node >= N_NODES) return;
    int row = g_rowptr[node], end = g_rowptr[node + 1];
    float4 acc = make_float4(0.f, 0.f, 0.f, 0.f);
    const __half2* ph = (const __half2*)g_ph;   // [node*64 + lane*2]
    int j = row;
    for (; j + 2 <= end; j += 2) {
        int s0 = __ldg(g_eidx + j), s1 = __ldg(g_eidx + j + 1);
        __half2 a0 = ph[s0 * 64 + lane * 2], b0 = ph[s0 * 64 + lane * 2 + 1];
        __half2 a1 = ph[s1 * 64 + lane * 2], b1 = ph[s1 * 64 + lane * 2 + 1];
        float2 f0 = __half22float2(a0), f1 = __half22float2(b0);
        float2 f2 = __half22float2(a1), f3 = __half22float2(b1);
        acc.x += f0.x + f2.x; acc.y += f0.y + f2.y;
        acc.z += f1.x + f3.x; acc.w += f1.y + f3.y;
    }
    for (; j < end; j++) {
        int s = __ldg(g_eidx + j);
        float2 f0 = __half22float2(ph[s * 64 + lane * 2]);
        float2 f1 = __half22float2(ph[s * 64 + lane * 2 + 1]);
        acc.x += f0.x; acc.y += f0.y; acc.z += f1.x; acc.w += f1.y;
    }
    float invd = 1.0f / fmaxf((float)(end - row), 1.0f);
    float4 r = g_r2[node * 32 + lane];
    float4 bb = ((const float4*)b2)[lane];
    float4 o;
    o.x = acc.x * invd + bb.x + r.x;
    o.y = acc.y * invd + bb.y + r.y;
    o.z = acc.z * invd + bb.z + r.z;
    o.w = acc.w * invd + bb.w + r.w;
    out[node * 32 + lane] = o;
}

// ---- pack weights to fp16, [out][k] layout ----
__global__ void prep_weights(const float* __restrict__ W1l, const float* __restrict__ W1r,
                             const float* __restrict__ W2l, const float* __restrict__ W2r) {
    int i = blockIdx.x * blockDim.x + threadIdx.x;
    if (i >= 256 * 256) return;
    int n = i >> 8, k = i & 255;
    g_W1h[i] = __float2half_rn((k < 128) ? W1l[n * 128 + k] : W1r[n * 128 + (k - 128)]);
    g_W2h[i] = __float2half_rn((n < 128) ? W2l[n * 256 + k] : W2r[(n - 128) * 256 + k]);
}

// ================= FP16 tensor-core fused double-GEMM =================
// 64 nodes x 256 outs per CTA. 8 warps: warp w owns n cols [w*32, w*32+32).
// sA [64][264] halves (A, then reused for h). sB 2x [256][72] halves (k-chunks of 64).
#define SA_H 264
#define SB_H 72
#define SA_HALFS (64 * SA_H)
#define SB_HALFS (256 * SB_H)
#define SMEM_BYTES ((SA_HALFS + 2 * SB_HALFS) * 2)

__device__ __forceinline__ void cp16h(__half* dst, const __half* src) {
    uint32_t sa = (uint32_t)__cvta_generic_to_shared(dst);
    asm volatile("cp.async.ca.shared.global [%0], [%1], 16;" :: "r"(sa), "l"(src));
}
__device__ __forceinline__ void cp_commit() { asm volatile("cp.async.commit_group;"); }
__device__ __forceinline__ void cp_wait0()  { asm volatile("cp.async.wait_group 0;"); }

// load one 64-k chunk of W[n=0..255][k=kc*64 .. +64) into buf[256][72]
__device__ __forceinline__ void load_chunkB(__half* buf, const __half* Wg, int kc, int tid) {
#pragma unroll
    for (int i = 0; i < 8; i++) {
        int idx = tid + i * 256;     // 0..2047
        int n = idx >> 3, c8 = idx & 7;
        cp16h(buf + n * SB_H + c8 * 8, Wg + n * 256 + kc * 64 + c8 * 8);
    }
}

__device__ __forceinline__ void mma_f16(float* d, uint32_t a0, uint32_t a1, uint32_t a2,
                                        uint32_t a3, uint32_t b0, uint32_t b1) {
    asm volatile(
        "mma.sync.aligned.m16n8k16.row.col.f32.f16.f16.f32 "
        "{%0,%1,%2,%3}, {%4,%5,%6,%7}, {%8,%9}, {%0,%1,%2,%3};"
        : "+f"(d[0]), "+f"(d[1]), "+f"(d[2]), "+f"(d[3])
        : "r"(a0), "r"(a1), "r"(a2), "r"(a3), "r"(b0), "r"(b1));
}

// one 256-K fp16 GEMM: acc += A(64x256 smem) @ Wg(256n x 256k, row=n)^T
__device__ __forceinline__ void gemm_fp16(const __half* A, const __half* Wg, const __half* WgNext,
                                          __half* sB0, __half* sB1,
                                          float acc[4][4][4], int tid, int lane, int n_base) {
    __half* sb[2] = {sB0, sB1};
    for (int kc = 0; kc < 4; kc++) {
        cp_wait0();
        __syncthreads();
        if (kc < 3)      { load_chunkB(sb[(kc + 1) & 1], Wg, kc + 1, tid); cp_commit(); }
        else if (WgNext) { load_chunkB(sb[0], WgNext, 0, tid); cp_commit(); }
        const __half* B = sb[kc & 1];
#pragma unroll
        for (int ksl = 0; ksl < 4; ksl++) {
            uint32_t bf[4][2];
#pragma unroll
            for (int nt = 0; nt < 4; nt++) {
                int n = n_base + nt * 8 + (lane & 7);
                int kl = ksl * 16 + ((lane >> 3) & 1) * 8;
                uint32_t ad = (uint32_t)__cvta_generic_to_shared(B + n * SB_H + kl);
                asm volatile("ldmatrix.sync.aligned.m8n8.x2.shared.b16 {%0,%1}, [%2];"
                             : "=r"(bf[nt][0]), "=r"(bf[nt][1]) : "r"(ad));
            }
#pragma unroll
            for (int mt = 0; mt < 4; mt++) {
                int m = mt * 16 + (lane & 15);
                int kk = kc * 64 + ksl * 16 + (lane >> 4) * 8;
                uint32_t ad = (uint32_t)__cvta_generic_to_shared(A + m * SA_H + kk);
                uint32_t a0, a1, a2, a3;
                asm volatile("ldmatrix.sync.aligned.m8n8.x4.shared.b16 {%0,%1,%2,%3}, [%4];"
                             : "=r"(a0), "=r"(a1), "=r"(a2), "=r"(a3) : "r"(ad));
#pragma unroll
                for (int nt = 0; nt < 4; nt++)
                    mma_f16(acc[mt][nt], a0, a1, a2, a3, bf[nt][0], bf[nt][1]);
            }
        }
    }
}

__global__ __launch_bounds__(256, 2) void gemm_mma_h(const float4* __restrict__ x,
                                                     const float* __restrict__ b1) {
    extern __shared__ __half smem_h[];
    __half* sA  = smem_h;
    __half* sB0 = smem_h + SA_HALFS;
    __half* sB1 = sB0 + SB_HALFS;

    int tid = threadIdx.x, lane = tid & 31, warp = tid >> 5;
    int node0 = blockIdx.x * 64;
    int n_base = warp * 32;

    // prologue: start W1 chunk 0, then stage A = [mean1 || x] (fp16)
    load_chunkB(sB0, g_W1h, 0, tid);
    cp_commit();

#pragma unroll
    for (int i = tid; i < 64 * 64; i += 256) {
        int n = i >> 6, c4 = i & 63;
        int node = node0 + n;
        if (node >= N_NODES) node = N_NODES - 1;
        float4 v = (c4 < 32) ? g_agg1[node * 32 + c4] : x[node * 32 + (c4 - 32)];
        __half* d = sA + n * SA_H + c4 * 4;
        *(__half2*)(d)     = __floats2half2_rn(v.x, v.y);
        *(__half2*)(d + 2) = __floats2half2_rn(v.z, v.w);
    }

    float acc[4][4][4];
#pragma unroll
    for (int a = 0; a < 4; a++)
#pragma unroll
        for (int b = 0; b < 4; b++)
#pragma unroll
            for (int c = 0; c < 4; c++) acc[a][b][c] = 0.f;

    // ---- GEMM1 (prefetches W2 chunk0 during its last chunk) ----
    gemm_fp16(sA, g_W1h, g_W2h, sB0, sB1, acc, tid, lane, n_base);

    // all warps done reading A before h overwrites it
    __syncthreads();

    // epilogue 1: bias + relu -> sA as fp16 h
#pragma unroll
    for (int mt = 0; mt < 4; mt++) {
        int row = mt * 16 + (lane >> 2);
#pragma unroll
        for (int nt = 0; nt < 4; nt++) {
            int col = n_base + nt * 8 + (lane & 3) * 2;
            float bb0 = __ldg(b1 + col), bb1 = __ldg(b1 + col + 1);
            *(__half2*)(sA + row * SA_H + col) =
                __floats2half2_rn(fmaxf(acc[mt][nt][0] + bb0, 0.f),
                                  fmaxf(acc[mt][nt][1] + bb1, 0.f));
            *(__half2*)(sA + (row + 8) * SA_H + col) =
                __floats2half2_rn(fmaxf(acc[mt][nt][2] + bb0, 0.f),
                                  fmaxf(acc[mt][nt][3] + bb1, 0.f));
            acc[mt][nt][0] = acc[mt][nt][1] = acc[mt][nt][2] = acc[mt][nt][3] = 0.f;
        }
    }

    // ---- GEMM2: [p || r2] = h @ W2h^T (first wait+sync fences h stores) ----
    gemm_fp16(sA, g_W2h, nullptr, sB0, sB1, acc, tid, lane, n_base);

    // store p (cols<128, fp16) / r2 (cols>=128, fp32)
    float* gr = (float*)g_r2;
#pragma unroll
    for (int mt = 0; mt < 4; mt++) {
        int row = mt * 16 + (lane >> 2);
#pragma unroll
        for (int nt = 0; nt < 4; nt++) {
            int col = n_base + nt * 8 + (lane & 3) * 2;
            int node = node0 + row;
            if (col < 128) {
                if (node < N_NODES)
                    *(__half2*)(g_ph + node * 128 + col) =
                        __floats2half2_rn(acc[mt][nt][0], acc[mt][nt][1]);
                if (node + 8 < N_NODES)
                    *(__half2*)(g_ph + (node + 8) * 128 + col) =
                        __floats2half2_rn(acc[mt][nt][2], acc[mt][nt][3]);
            } else {
                int cc = col - 128;
                if (node < N_NODES)
                    *(float2*)(gr + node * 128 + cc) = make_float2(acc[mt][nt][0], acc[mt][nt][1]);
                if (node + 8 < N_NODES)
                    *(float2*)(gr + (node + 8) * 128 + cc) = make_float2(acc[mt][nt][2], acc[mt][nt][3]);
            }
        }
    }
}

extern "C" void kernel_launch(void* const* d_in, const int* in_sizes, int n_in,
                              void* d_out, int out_size) {
    const float4* x   = (const float4*)d_in[0];
    const int*    ei  = (const int*)d_in[1];
    const float*  W1l = (const float*)d_in[2];
    const float*  b1  = (const float*)d_in[3];
    const float*  W1r = (const float*)d_in[4];
    const float*  W2l = (const float*)d_in[5];
    const float*  b2  = (const float*)d_in[6];
    const float*  W2r = (const float*)d_in[7];
    int E = in_sizes[1] / 2;

    cudaFuncSetAttribute(gemm_mma_h, cudaFuncAttributeMaxDynamicSharedMemorySize, SMEM_BYTES);

    zero_cnt<<<(N_NODES + 255) / 256, 256>>>();
    hist_kernel<<<(E + 255) / 256, 256>>>(ei, E);
    scan_rowptr<<<1, 1024>>>(E);
    fill_kernel<<<(E + 255) / 256, 256>>>(ei, E);
    prep_weights<<<(256 * 256 + 255) / 256, 256>>>(W1l, W1r, W2l, W2r);
    agg_mean_x<<<(N_NODES + 7) / 8, 256>>>(x);
    gemm_mma_h<<<(N_NODES + 63) / 64, 256, SMEM_BYTES>>>(x, b1);
    agg_final<<<(N_NODES + 7) / 8, 256>>>(b2, (float4*)d_out);
}

// round 8
// speedup vs baseline: 3.9387x; 1.0562x over previous
#include <cuda_runtime.h>
#include <cuda_fp16.h>
#include <cstdint>

#define N_NODES 50000
#define E_MAX   800000

// ---- scratch (static __device__ — no allocations allowed) ----
__device__ __align__(16) __half g_xh  [N_NODES * 128];  // x in fp16
__device__ __align__(16) __half g_aggh[N_NODES * 128];  // MEAN of x[src] per dst (fp16)
__device__ __align__(16) __half g_ph  [N_NODES * 128];  // h @ W2_l.T  (fp16)
__device__ __align__(16) float4 g_r2  [N_NODES * 32];   // h @ W2_r.T  (fp32)
__device__ __align__(16) __half g_W1h [256 * 256];      // [t][k] fp16; k<128 -> W1_l else W1_r
__device__ __align__(16) __half g_W2h [256 * 256];      // [j][k] fp16; j<128 -> W2_l else W2_r
// CSR by dst
__device__ int g_cnt [N_NODES];
__device__ int g_fill[N_NODES];
__device__ int g_rowptr[N_NODES + 1];
__device__ int g_eidx[E_MAX];

// ================= CSR build =================
__global__ void zero_cnt() {
    int i = blockIdx.x * blockDim.x + threadIdx.x;
    if (i < N_NODES) g_cnt[i] = 0;
}
__global__ void hist_kernel(const int* __restrict__ ei, int E) {
    int e = blockIdx.x * blockDim.x + threadIdx.x;
    if (e < E) atomicAdd(&g_cnt[ei[E + e]], 1);
}
__global__ void scan_rowptr(int E) {
    __shared__ int part[1024];
    const int CH = (N_NODES + 1023) / 1024;
    int t = threadIdx.x;
    int begin = t * CH, end = min(begin + CH, N_NODES);
    int s = 0;
    for (int i = begin; i < end; i++) s += g_cnt[i];
    part[t] = s;
    __syncthreads();
    for (int off = 1; off < 1024; off <<= 1) {
        int add = (t >= off) ? part[t - off] : 0;
        __syncthreads();
        part[t] += add;
        __syncthreads();
    }
    int run = part[t] - s;
    for (int i = begin; i < end; i++) {
        g_rowptr[i] = run;
        g_fill[i] = run;
        run += g_cnt[i];
    }
    if (t == 1023) g_rowptr[N_NODES] = E;
}
__global__ void fill_kernel(const int* __restrict__ ei, int E) {
    int e = blockIdx.x * blockDim.x + threadIdx.x;
    if (e >= E) return;
    int s = ei[e];
    int d = ei[E + e];
    int pos = atomicAdd(&g_fill[d], 1);
    g_eidx[pos] = s;
}

// ---- x -> fp16 ----
__global__ void convert_x(const float4* __restrict__ x) {
    int i = blockIdx.x * blockDim.x + threadIdx.x;
    if (i >= N_NODES * 32) return;
    float4 v = x[i];
    __half2* d = (__half2*)(g_xh + i * 4);
    d[0] = __floats2half2_rn(v.x, v.y);
    d[1] = __floats2half2_rn(v.z, v.w);
}

// ---- pack weights to fp16, [out][k] layout ----
__global__ void prep_weights(const float* __restrict__ W1l, const float* __restrict__ W1r,
                             const float* __restrict__ W2l, const float* __restrict__ W2r) {
    int i = blockIdx.x * blockDim.x + threadIdx.x;
    if (i >= 256 * 256) return;
    int n = i >> 8, k = i & 255;
    g_W1h[i] = __float2half_rn((k < 128) ? W1l[n * 128 + k] : W1r[n * 128 + (k - 128)]);
    g_W2h[i] = __float2half_rn((n < 128) ? W2l[n * 256 + k] : W2r[(n - 128) * 256 + k]);
}

// ================= gather-side aggregation (fp16 payload, fp32 accum) =================
// one warp per node; lane owns 4 halves (uint2 = 8B) of the 128-half feature row.
__device__ __forceinline__ void acc_u2(float4& acc, uint2 u) {
    float2 f0 = __half22float2(*(__half2*)&u.x);
    float2 f1 = __half22float2(*(__half2*)&u.y);
    acc.x += f0.x; acc.y += f0.y; acc.z += f1.x; acc.w += f1.y;
}

template <int FINAL>
__global__ void agg_gather(const float* __restrict__ b2, float4* __restrict__ out) {
    int node = blockIdx.x * 8 + (threadIdx.x >> 5);
    int lane = threadIdx.x & 31;
    if (node >= N_NODES) return;
    int row = g_rowptr[node], end = g_rowptr[node + 1];
    const uint2* feat = (const uint2*)(FINAL ? g_ph : g_xh);   // [node*32 + lane]
    float4 acc = make_float4(0.f, 0.f, 0.f, 0.f);
    int j = row;
    for (; j + 4 <= end; j += 4) {
        int s0 = __ldg(g_eidx + j), s1 = __ldg(g_eidx + j + 1);
        int s2 = __ldg(g_eidx + j + 2), s3 = __ldg(g_eidx + j + 3);
        acc_u2(acc, feat[s0 * 32 + lane]);
        acc_u2(acc, feat[s1 * 32 + lane]);
        acc_u2(acc, feat[s2 * 32 + lane]);
        acc_u2(acc, feat[s3 * 32 + lane]);
    }
    for (; j < end; j++) {
        int s = __ldg(g_eidx + j);
        acc_u2(acc, feat[s * 32 + lane]);
    }
    float invd = 1.0f / fmaxf((float)(end - row), 1.0f);
    acc.x *= invd; acc.y *= invd; acc.z *= invd; acc.w *= invd;
    if (FINAL) {
        float4 r = g_r2[node * 32 + lane];
        float4 bb = ((const float4*)b2)[lane];
        float4 o;
        o.x = acc.x + bb.x + r.x;
        o.y = acc.y + bb.y + r.y;
        o.z = acc.z + bb.z + r.z;
        o.w = acc.w + bb.w + r.w;
        out[node * 32 + lane] = o;
    } else {
        __half2* d = (__half2*)(g_aggh + node * 128 + lane * 4);
        d[0] = __floats2half2_rn(acc.x, acc.y);
        d[1] = __floats2half2_rn(acc.z, acc.w);
    }
}

// ================= FP16 tensor-core fused double-GEMM =================
// 64 nodes x 256 outs per CTA. 8 warps: warp w owns n cols [w*32, w*32+32).
// sA [64][264] halves (A, then reused for h). sB 2x [256][72] halves (k-chunks of 64).
#define SA_H 264
#define SB_H 72
#define SA_HALFS (64 * SA_H)
#define SB_HALFS (256 * SB_H)
#define SMEM_BYTES ((SA_HALFS + 2 * SB_HALFS) * 2)

__device__ __forceinline__ void cp16h(__half* dst, const __half* src) {
    uint32_t sa = (uint32_t)__cvta_generic_to_shared(dst);
    asm volatile("cp.async.ca.shared.global [%0], [%1], 16;" :: "r"(sa), "l"(src));
}
__device__ __forceinline__ void cp_commit() { asm volatile("cp.async.commit_group;"); }
__device__ __forceinline__ void cp_wait0()  { asm volatile("cp.async.wait_group 0;"); }

// load one 64-k chunk of W[n=0..255][k=kc*64 .. +64) into buf[256][72]
__device__ __forceinline__ void load_chunkB(__half* buf, const __half* Wg, int kc, int tid) {
#pragma unroll
    for (int i = 0; i < 8; i++) {
        int idx = tid + i * 256;     // 0..2047
        int n = idx >> 3, c8 = idx & 7;
        cp16h(buf + n * SB_H + c8 * 8, Wg + n * 256 + kc * 64 + c8 * 8);
    }
}

__device__ __forceinline__ void mma_f16(float* d, uint32_t a0, uint32_t a1, uint32_t a2,
                                        uint32_t a3, uint32_t b0, uint32_t b1) {
    asm volatile(
        "mma.sync.aligned.m16n8k16.row.col.f32.f16.f16.f32 "
        "{%0,%1,%2,%3}, {%4,%5,%6,%7}, {%8,%9}, {%0,%1,%2,%3};"
        : "+f"(d[0]), "+f"(d[1]), "+f"(d[2]), "+f"(d[3])
        : "r"(a0), "r"(a1), "r"(a2), "r"(a3), "r"(b0), "r"(b1));
}

// one 256-K fp16 GEMM: acc += A(64x256 smem) @ Wg(256n x 256k, row=n)^T
__device__ __forceinline__ void gemm_fp16(const __half* A, const __half* Wg, const __half* WgNext,
                                          __half* sB0, __half* sB1,
                                          float acc[4][4][4], int tid, int lane, int n_base) {
    __half* sb[2] = {sB0, sB1};
    for (int kc = 0; kc < 4; kc++) {
        cp_wait0();
        __syncthreads();
        if (kc < 3)      { load_chunkB(sb[(kc + 1) & 1], Wg, kc + 1, tid); cp_commit(); }
        else if (WgNext) { load_chunkB(sb[0], WgNext, 0, tid); cp_commit(); }
        const __half* B = sb[kc & 1];
#pragma unroll
        for (int ksl = 0; ksl < 4; ksl++) {
            uint32_t bf[4][2];
#pragma unroll
            for (int nt = 0; nt < 4; nt++) {
                int n = n_base + nt * 8 + (lane & 7);
                int kl = ksl * 16 + ((lane >> 3) & 1) * 8;
                uint32_t ad = (uint32_t)__cvta_generic_to_shared(B + n * SB_H + kl);
                asm volatile("ldmatrix.sync.aligned.m8n8.x2.shared.b16 {%0,%1}, [%2];"
                             : "=r"(bf[nt][0]), "=r"(bf[nt][1]) : "r"(ad));
            }
#pragma unroll
            for (int mt = 0; mt < 4; mt++) {
                int m = mt * 16 + (lane & 15);
                int kk = kc * 64 + ksl * 16 + (lane >> 4) * 8;
                uint32_t ad = (uint32_t)__cvta_generic_to_shared(A + m * SA_H + kk);
                uint32_t a0, a1, a2, a3;
                asm volatile("ldmatrix.sync.aligned.m8n8.x4.shared.b16 {%0,%1,%2,%3}, [%4];"
                             : "=r"(a0), "=r"(a1), "=r"(a2), "=r"(a3) : "r"(ad));
#pragma unroll
                for (int nt = 0; nt < 4; nt++)
                    mma_f16(acc[mt][nt], a0, a1, a2, a3, bf[nt][0], bf[nt][1]);
            }
        }
    }
}

__global__ __launch_bounds__(256, 2) void gemm_mma_h(const float* __restrict__ b1) {
    extern __shared__ __half smem_h[];
    __half* sA  = smem_h;
    __half* sB0 = smem_h + SA_HALFS;
    __half* sB1 = sB0 + SB_HALFS;

    int tid = threadIdx.x, lane = tid & 31, warp = tid >> 5;
    int node0 = blockIdx.x * 64;
    int n_base = warp * 32;

    // prologue: B chunk 0 + A staging, all via cp.async (one wait covers both)
    load_chunkB(sB0, g_W1h, 0, tid);

    // stage A = [mean1 || x] fp16: 2048 16B copies (64 nodes x 32 col-groups)
#pragma unroll
    for (int i = 0; i < 8; i++) {
        int idx = tid + i * 256;
        int n = idx >> 5, c8 = idx & 31;      // c8: 8-half group
        int node = node0 + n;
        if (node >= N_NODES) node = N_NODES - 1;
        const __half* src = (c8 < 16) ? (g_aggh + node * 128 + c8 * 8)
                                      : (g_xh  + node * 128 + (c8 - 16) * 8);
        cp16h(sA + n * SA_H + c8 * 8, src);
    }
    cp_commit();

    float acc[4][4][4];
#pragma unroll
    for (int a = 0; a < 4; a++)
#pragma unroll
        for (int b = 0; b < 4; b++)
#pragma unroll
            for (int c = 0; c < 4; c++) acc[a][b][c] = 0.f;

    // ---- GEMM1 (prefetches W2 chunk0 during its last chunk) ----
    gemm_fp16(sA, g_W1h, g_W2h, sB0, sB1, acc, tid, lane, n_base);

    // all warps done reading A before h overwrites it
    __syncthreads();

    // epilogue 1: bias + relu -> sA as fp16 h
#pragma unroll
    for (int mt = 0; mt < 4; mt++) {
        int row = mt * 16 + (lane >> 2);
#pragma unroll
        for (int nt = 0; nt < 4; nt++) {
            int col = n_base + nt * 8 + (lane & 3) * 2;
            float bb0 = __ldg(b1 + col), bb1 = __ldg(b1 + col + 1);
            *(__half2*)(sA + row * SA_H + col) =
                __floats2half2_rn(fmaxf(acc[mt][nt][0] + bb0, 0.f),
                                  fmaxf(acc[mt][nt][1] + bb1, 0.f));
            *(__half2*)(sA + (row + 8) * SA_H + col) =
                __floats2half2_rn(fmaxf(acc[mt][nt][2] + bb0, 0.f),
                                  fmaxf(acc[mt][nt][3] + bb1, 0.f));
            acc[mt][nt][0] = acc[mt][nt][1] = acc[mt][nt][2] = acc[mt][nt][3] = 0.f;
        }
    }

    // ---- GEMM2: [p || r2] = h @ W2h^T (first wait+sync fences h stores) ----
    gemm_fp16(sA, g_W2h, nullptr, sB0, sB1, acc, tid, lane, n_base);

    // store p (cols<128, fp16) / r2 (cols>=128, fp32)
    float* gr = (float*)g_r2;
#pragma unroll
    for (int mt = 0; mt < 4; mt++) {
        int row = mt * 16 + (lane >> 2);
#pragma unroll
        for (int nt = 0; nt < 4; nt++) {
            int col = n_base + nt * 8 + (lane & 3) * 2;
            int node = node0 + row;
            if (col < 128) {
                if (node < N_NODES)
                    *(__half2*)(g_ph + node * 128 + col) =
                        __floats2half2_rn(acc[mt][nt][0], acc[mt][nt][1]);
                if (node + 8 < N_NODES)
                    *(__half2*)(g_ph + (node + 8) * 128 + col) =
                        __floats2half2_rn(acc[mt][nt][2], acc[mt][nt][3]);
            } else {
                int cc = col - 128;
                if (node < N_NODES)
                    *(float2*)(gr + node * 128 + cc) = make_float2(acc[mt][nt][0], acc[mt][nt][1]);
                if (node + 8 < N_NODES)
                    *(float2*)(gr + (node + 8) * 128 + cc) = make_float2(acc[mt][nt][2], acc[mt][nt][3]);
            }
        }
    }
}

extern "C" void kernel_launch(void* const* d_in, const int* in_sizes, int n_in,
                              void* d_out, int out_size) {
    const float4* x   = (const float4*)d_in[0];
    const int*    ei  = (const int*)d_in[1];
    const float*  W1l = (const float*)d_in[2];
    const float*  b1  = (const float*)d_in[3];
    const float*  W1r = (const float*)d_in[4];
    const float*  W2l = (const float*)d_in[5];
    const float*  b2  = (const float*)d_in[6];
    const float*  W2r = (const float*)d_in[7];
    int E = in_sizes[1] / 2;

    cudaFuncSetAttribute(gemm_mma_h, cudaFuncAttributeMaxDynamicSharedMemorySize, SMEM_BYTES);

    zero_cnt<<<(N_NODES + 255) / 256, 256>>>();
    hist_kernel<<<(E + 255) / 256, 256>>>(ei, E);
    convert_x<<<(N_NODES * 32 + 255) / 256, 256>>>(x);
    scan_rowptr<<<1, 1024>>>(E);
    fill_kernel<<<(E + 255) / 256, 256>>>(ei, E);
    prep_weights<<<(256 * 256 + 255) / 256, 256>>>(W1l, W1r, W2l, W2r);
    agg_gather<0><<<(N_NODES + 7) / 8, 256>>>(nullptr, nullptr);
    gemm_mma_h<<<(N_NODES + 63) / 64, 256, SMEM_BYTES>>>(b1);
    agg_gather<1><<<(N_NODES + 7) / 8, 256>>>(b2, (float4*)d_out);
}

// round 9
// speedup vs baseline: 5.9544x; 1.5118x over previous
#include <cuda_runtime.h>
#include <cuda_fp16.h>
#include <cstdint>

#define N_NODES 50000
#define E_MAX   800000
#define SCAN_CHUNK 4096
#define NB_SCAN ((N_NODES + SCAN_CHUNK - 1) / SCAN_CHUNK)   // 13

// ---- scratch (static __device__ — no allocations allowed) ----
__device__ __align__(16) __half g_xh  [N_NODES * 128];  // x in fp16
__device__ __align__(16) __half g_aggh[N_NODES * 128];  // MEAN of x[src] per dst (fp16)
__device__ __align__(16) __half g_ph  [N_NODES * 128];  // h @ W2_l.T  (fp16)
__device__ __align__(16) float4 g_r2  [N_NODES * 32];   // h @ W2_r.T  (fp32)
__device__ __align__(16) __half g_W1h [256 * 256];      // [t][k] fp16
__device__ __align__(16) __half g_W2h [256 * 256];      // [j][k] fp16
// CSR by dst
__device__ __align__(16) int g_cnt [N_NODES];
__device__ int g_fill[N_NODES];
__device__ int g_rowptr[N_NODES + 1];
__device__ int g_eidx[E_MAX];
__device__ int g_bsum[NB_SCAN];
__device__ int g_boff[NB_SCAN];

// ================= CSR build =================
__global__ void zero_cnt() {
    int i = blockIdx.x * blockDim.x + threadIdx.x;
    if (i < N_NODES) g_cnt[i] = 0;
}
__global__ void hist_kernel(const int* __restrict__ ei, int E) {
    int e = blockIdx.x * blockDim.x + threadIdx.x;
    if (e < E) atomicAdd(&g_cnt[ei[E + e]], 1);
}

// pass 1: block-local exclusive scan (1024 thr x 4 elems), block totals to g_bsum
__global__ __launch_bounds__(1024) void scan1() {
    __shared__ int wsum[32];
    int t = threadIdx.x, lane = t & 31, wid = t >> 5;
    int base = blockIdx.x * SCAN_CHUNK + t * 4;
    int v0 = 0, v1 = 0, v2 = 0, v3 = 0;
    if (base + 3 < N_NODES) {
        int4 v = *(const int4*)(g_cnt + base);
        v0 = v.x; v1 = v.y; v2 = v.z; v3 = v.w;
    } else {
        if (base + 0 < N_NODES) v0 = g_cnt[base + 0];
        if (base + 1 < N_NODES) v1 = g_cnt[base + 1];
        if (base + 2 < N_NODES) v2 = g_cnt[base + 2];
        if (base + 3 < N_NODES) v3 = g_cnt[base + 3];
    }
    int s = v0 + v1 + v2 + v3;
    int inc = s;
#pragma unroll
    for (int off = 1; off < 32; off <<= 1) {
        int n = __shfl_up_sync(0xffffffff, inc, off);
        if (lane >= off) inc += n;
    }
    if (lane == 31) wsum[wid] = inc;
    __syncthreads();
    if (wid == 0) {
        int w = wsum[lane];
#pragma unroll
        for (int off = 1; off < 32; off <<= 1) {
            int n = __shfl_up_sync(0xffffffff, w, off);
            if (lane >= off) w += n;
        }
        wsum[lane] = w;
    }
    __syncthreads();
    int excl = inc - s + (wid > 0 ? wsum[wid - 1] : 0);
    if (base + 0 < N_NODES) g_rowptr[base + 0] = excl;       excl += v0;
    if (base + 1 < N_NODES) g_rowptr[base + 1] = excl;       excl += v1;
    if (base + 2 < N_NODES) g_rowptr[base + 2] = excl;       excl += v2;
    if (base + 3 < N_NODES) g_rowptr[base + 3] = excl;
    if (t == 0) g_bsum[blockIdx.x] = wsum[31];
}

// pass 2: one warp scans the block totals (exclusive)
__global__ void scan2() {
    int lane = threadIdx.x;
    int v = (lane < NB_SCAN) ? g_bsum[lane] : 0;
    int inc = v;
#pragma unroll
    for (int off = 1; off < 32; off <<= 1) {
        int n = __shfl_up_sync(0xffffffff, inc, off);
        if (lane >= off) inc += n;
    }
    if (lane < NB_SCAN) g_boff[lane] = inc - v;
}

// pass 3: add block offsets; init fill; cap rowptr
__global__ void scan3(int E) {
    int i = blockIdx.x * blockDim.x + threadIdx.x;
    if (i < N_NODES) {
        int r = g_rowptr[i] + g_boff[i / SCAN_CHUNK];
        g_rowptr[i] = r;
        g_fill[i] = r;
    }
    if (i == 0) g_rowptr[N_NODES] = E;
}

__global__ void fill_kernel(const int* __restrict__ ei, int E) {
    int e = blockIdx.x * blockDim.x + threadIdx.x;
    if (e >= E) return;
    int s = ei[e];
    int d = ei[E + e];
    int pos = atomicAdd(&g_fill[d], 1);
    g_eidx[pos] = s;
}

// ---- x -> fp16 ----
__global__ void convert_x(const float4* __restrict__ x) {
    int i = blockIdx.x * blockDim.x + threadIdx.x;
    if (i >= N_NODES * 32) return;
    float4 v = x[i];
    __half2* d = (__half2*)(g_xh + i * 4);
    d[0] = __floats2half2_rn(v.x, v.y);
    d[1] = __floats2half2_rn(v.z, v.w);
}

// ---- pack weights to fp16, [out][k] layout ----
__global__ void prep_weights(const float* __restrict__ W1l, const float* __restrict__ W1r,
                             const float* __restrict__ W2l, const float* __restrict__ W2r) {
    int i = blockIdx.x * blockDim.x + threadIdx.x;
    if (i >= 256 * 256) return;
    int n = i >> 8, k = i & 255;
    g_W1h[i] = __float2half_rn((k < 128) ? W1l[n * 128 + k] : W1r[n * 128 + (k - 128)]);
    g_W2h[i] = __float2half_rn((n < 128) ? W2l[n * 256 + k] : W2r[(n - 128) * 256 + k]);
}

// ================= gather-side aggregation (fp16 payload, fp32 accum) =================
__device__ __forceinline__ void acc_u2(float4& acc, uint2 u) {
    float2 f0 = __half22float2(*(__half2*)&u.x);
    float2 f1 = __half22float2(*(__half2*)&u.y);
    acc.x += f0.x; acc.y += f0.y; acc.z += f1.x; acc.w += f1.y;
}

template <int FINAL>
__global__ void agg_gather(const float* __restrict__ b2, float4* __restrict__ out) {
    int node = blockIdx.x * 8 + (threadIdx.x >> 5);
    int lane = threadIdx.x & 31;
    if (node >= N_NODES) return;
    int row = g_rowptr[node], end = g_rowptr[node + 1];
    const uint2* feat = (const uint2*)(FINAL ? g_ph : g_xh);   // [node*32 + lane]
    float4 acc = make_float4(0.f, 0.f, 0.f, 0.f);
    int j = row;
    for (; j + 4 <= end; j += 4) {
        int s0 = __ldg(g_eidx + j), s1 = __ldg(g_eidx + j + 1);
        int s2 = __ldg(g_eidx + j + 2), s3 = __ldg(g_eidx + j + 3);
        acc_u2(acc, feat[s0 * 32 + lane]);
        acc_u2(acc, feat[s1 * 32 + lane]);
        acc_u2(acc, feat[s2 * 32 + lane]);
        acc_u2(acc, feat[s3 * 32 + lane]);
    }
    for (; j < end; j++) {
        int s = __ldg(g_eidx + j);
        acc_u2(acc, feat[s * 32 + lane]);
    }
    float invd = 1.0f / fmaxf((float)(end - row), 1.0f);
    acc.x *= invd; acc.y *= invd; acc.z *= invd; acc.w *= invd;
    if (FINAL) {
        float4 r = g_r2[node * 32 + lane];
        float4 bb = ((const float4*)b2)[lane];
        float4 o;
        o.x = acc.x + bb.x + r.x;
        o.y = acc.y + bb.y + r.y;
        o.z = acc.z + bb.z + r.z;
        o.w = acc.w + bb.w + r.w;
        out[node * 32 + lane] = o;
    } else {
        __half2* d = (__half2*)(g_aggh + node * 128 + lane * 4);
        d[0] = __floats2half2_rn(acc.x, acc.y);
        d[1] = __floats2half2_rn(acc.z, acc.w);
    }
}

// ================= FP16 tensor-core fused double-GEMM =================
#define SA_H 264
#define SB_H 72
#define SA_HALFS (64 * SA_H)
#define SB_HALFS (256 * SB_H)
#define SMEM_BYTES ((SA_HALFS + 2 * SB_HALFS) * 2)

__device__ __forceinline__ void cp16h(__half* dst, const __half* src) {
    uint32_t sa = (uint32_t)__cvta_generic_to_shared(dst);
    asm volatile("cp.async.ca.shared.global [%0], [%1], 16;" :: "r"(sa), "l"(src));
}
__device__ __forceinline__ void cp_commit() { asm volatile("cp.async.commit_group;"); }
__device__ __forceinline__ void cp_wait0()  { asm volatile("cp.async.wait_group 0;"); }

__device__ __forceinline__ void load_chunkB(__half* buf, const __half* Wg, int kc, int tid) {
#pragma unroll
    for (int i = 0; i < 8; i++) {
        int idx = tid + i * 256;
        int n = idx >> 3, c8 = idx & 7;
        cp16h(buf + n * SB_H + c8 * 8, Wg + n * 256 + kc * 64 + c8 * 8);
    }
}

__device__ __forceinline__ void mma_f16(float* d, uint32_t a0, uint32_t a1, uint32_t a2,
                                        uint32_t a3, uint32_t b0, uint32_t b1) {
    asm volatile(
        "mma.sync.aligned.m16n8k16.row.col.f32.f16.f16.f32 "
        "{%0,%1,%2,%3}, {%4,%5,%6,%7}, {%8,%9}, {%0,%1,%2,%3};"
        : "+f"(d[0]), "+f"(d[1]), "+f"(d[2]), "+f"(d[3])
        : "r"(a0), "r"(a1), "r"(a2), "r"(a3), "r"(b0), "r"(b1));
}

__device__ __forceinline__ void gemm_fp16(const __half* A, const __half* Wg, const __half* WgNext,
                                          __half* sB0, __half* sB1,
                                          float acc[4][4][4], int tid, int lane, int n_base) {
    __half* sb[2] = {sB0, sB1};
    for (int kc = 0; kc < 4; kc++) {
        cp_wait0();
        __syncthreads();
        if (kc < 3)      { load_chunkB(sb[(kc + 1) & 1], Wg, kc + 1, tid); cp_commit(); }
        else if (WgNext) { load_chunkB(sb[0], WgNext, 0, tid); cp_commit(); }
        const __half* B = sb[kc & 1];
#pragma unroll
        for (int ksl = 0; ksl < 4; ksl++) {
            uint32_t bf[4][2];
#pragma unroll
            for (int nt = 0; nt < 4; nt++) {
                int n = n_base + nt * 8 + (lane & 7);
                int kl = ksl * 16 + ((lane >> 3) & 1) * 8;
                uint32_t ad = (uint32_t)__cvta_generic_to_shared(B + n * SB_H + kl);
                asm volatile("ldmatrix.sync.aligned.m8n8.x2.shared.b16 {%0,%1}, [%2];"
                             : "=r"(bf[nt][0]), "=r"(bf[nt][1]) : "r"(ad));
            }
#pragma unroll
            for (int mt = 0; mt < 4; mt++) {
                int m = mt * 16 + (lane & 15);
                int kk = kc * 64 + ksl * 16 + (lane >> 4) * 8;
                uint32_t ad = (uint32_t)__cvta_generic_to_shared(A + m * SA_H + kk);
                uint32_t a0, a1, a2, a3;
                asm volatile("ldmatrix.sync.aligned.m8n8.x4.shared.b16 {%0,%1,%2,%3}, [%4];"
                             : "=r"(a0), "=r"(a1), "=r"(a2), "=r"(a3) : "r"(ad));
#pragma unroll
                for (int nt = 0; nt < 4; nt++)
                    mma_f16(acc[mt][nt], a0, a1, a2, a3, bf[nt][0], bf[nt][1]);
            }
        }
    }
}

__global__ __launch_bounds__(256, 2) void gemm_mma_h(const float* __restrict__ b1) {
    extern __shared__ __half smem_h[];
    __half* sA  = smem_h;
    __half* sB0 = smem_h + SA_HALFS;
    __half* sB1 = sB0 + SB_HALFS;

    int tid = threadIdx.x, lane = tid & 31, warp = tid >> 5;
    int node0 = blockIdx.x * 64;
    int n_base = warp * 32;

    load_chunkB(sB0, g_W1h, 0, tid);
#pragma unroll
    for (int i = 0; i < 8; i++) {
        int idx = tid + i * 256;
        int n = idx >> 5, c8 = idx & 31;
        int node = node0 + n;
        if (node >= N_NODES) node = N_NODES - 1;
        const __half* src = (c8 < 16) ? (g_aggh + node * 128 + c8 * 8)
                                      : (g_xh  + node * 128 + (c8 - 16) * 8);
        cp16h(sA + n * SA_H + c8 * 8, src);
    }
    cp_commit();

    float acc[4][4][4];
#pragma unroll
    for (int a = 0; a < 4; a++)
#pragma unroll
        for (int b = 0; b < 4; b++)
#pragma unroll
            for (int c = 0; c < 4; c++) acc[a][b][c] = 0.f;

    gemm_fp16(sA, g_W1h, g_W2h, sB0, sB1, acc, tid, lane, n_base);

    __syncthreads();

#pragma unroll
    for (int mt = 0; mt < 4; mt++) {
        int row = mt * 16 + (lane >> 2);
#pragma unroll
        for (int nt = 0; nt < 4; nt++) {
            int col = n_base + nt * 8 + (lane & 3) * 2;
            float bb0 = __ldg(b1 + col), bb1 = __ldg(b1 + col + 1);
            *(__half2*)(sA + row * SA_H + col) =
                __floats2half2_rn(fmaxf(acc[mt][nt][0] + bb0, 0.f),
                                  fmaxf(acc[mt][nt][1] + bb1, 0.f));
            *(__half2*)(sA + (row + 8) * SA_H + col) =
                __floats2half2_rn(fmaxf(acc[mt][nt][2] + bb0, 0.f),
                                  fmaxf(acc[mt][nt][3] + bb1, 0.f));
            acc[mt][nt][0] = acc[mt][nt][1] = acc[mt][nt][2] = acc[mt][nt][3] = 0.f;
        }
    }

    gemm_fp16(sA, g_W2h, nullptr, sB0, sB1, acc, tid, lane, n_base);

    float* gr = (float*)g_r2;
#pragma unroll
    for (int mt = 0; mt < 4; mt++) {
        int row = mt * 16 + (lane >> 2);
#pragma unroll
        for (int nt = 0; nt < 4; nt++) {
            int col = n_base + nt * 8 + (lane & 3) * 2;
            int node = node0 + row;
            if (col < 128) {
                if (node < N_NODES)
                    *(__half2*)(g_ph + node * 128 + col) =
                        __floats2half2_rn(acc[mt][nt][0], acc[mt][nt][1]);
                if (node + 8 < N_NODES)
                    *(__half2*)(g_ph + (node + 8) * 128 + col) =
                        __floats2half2_rn(acc[mt][nt][2], acc[mt][nt][3]);
            } else {
                int cc = col - 128;
                if (node < N_NODES)
                    *(float2*)(gr + node * 128 + cc) = make_float2(acc[mt][nt][0], acc[mt][nt][1]);
                if (node + 8 < N_NODES)
                    *(float2*)(gr + (node + 8) * 128 + cc) = make_float2(acc[mt][nt][2], acc[mt][nt][3]);
            }
        }
    }
}

extern "C" void kernel_launch(void* const* d_in, const int* in_sizes, int n_in,
                              void* d_out, int out_size) {
    const float4* x   = (const float4*)d_in[0];
    const int*    ei  = (const int*)d_in[1];
    const float*  W1l = (const float*)d_in[2];
    const float*  b1  = (const float*)d_in[3];
    const float*  W1r = (const float*)d_in[4];
    const float*  W2l = (const float*)d_in[5];
    const float*  b2  = (const float*)d_in[6];
    const float*  W2r = (const float*)d_in[7];
    int E = in_sizes[1] / 2;

    cudaFuncSetAttribute(gemm_mma_h, cudaFuncAttributeMaxDynamicSharedMemorySize, SMEM_BYTES);

    zero_cnt<<<(N_NODES + 255) / 256, 256>>>();
    hist_kernel<<<(E + 255) / 256, 256>>>(ei, E);
    convert_x<<<(N_NODES * 32 + 255) / 256, 256>>>(x);
    scan1<<<NB_SCAN, 1024>>>();
    scan2<<<1, 32>>>();
    scan3<<<(N_NODES + 255) / 256, 256>>>(E);
    fill_kernel<<<(E + 255) / 256, 256>>>(ei, E);
    prep_weights<<<(256 * 256 + 255) / 256, 256>>>(W1l, W1r, W2l, W2r);
    agg_gather<0><<<(N_NODES + 7) / 8, 256>>>(nullptr, nullptr);
    gemm_mma_h<<<(N_NODES + 63) / 64, 256, SMEM_BYTES>>>(b1);
    agg_gather<1><<<(N_NODES + 7) / 8, 256>>>(b2, (float4*)d_out);
}

// round 11
// speedup vs baseline: 6.1737x; 1.0368x over previous
#include <cuda_runtime.h>
#include <cuda_fp16.h>
#include <cstdint>

#define N_NODES 50000
#define E_MAX   800000
#define SCAN_CHUNK 4096
#define NB_SCAN ((N_NODES + SCAN_CHUNK - 1) / SCAN_CHUNK)   // 13

// ---- scratch (static __device__ — no allocations allowed) ----
__device__ __align__(16) __half g_xh  [N_NODES * 128];  // x in fp16
__device__ __align__(16) __half g_aggh[N_NODES * 128];  // MEAN of x[src] per dst (fp16)
__device__ __align__(16) __half g_ph  [N_NODES * 128];  // h @ W2_l.T  (fp16)
__device__ __align__(16) float4 g_r2  [N_NODES * 32];   // h @ W2_r.T  (fp32)
__device__ __align__(16) __half g_W1h [256 * 256];      // [t][k] fp16
__device__ __align__(16) __half g_W2h [256 * 256];      // [j][k] fp16
// CSR by dst
__device__ __align__(16) int g_cnt [N_NODES];
__device__ int g_fill[N_NODES];
__device__ int g_rowptr[N_NODES + 1];
__device__ int g_eidx[E_MAX];
__device__ int g_bsum[NB_SCAN];
__device__ int g_boff[NB_SCAN];

// ================= fused prep: zero cnt + x->fp16 + weights->fp16 =================
#define PREP_TOTAL (N_NODES * 32 + N_NODES + 256 * 256)
__global__ void prep_all(const float4* __restrict__ x,
                         const float* __restrict__ W1l, const float* __restrict__ W1r,
                         const float* __restrict__ W2l, const float* __restrict__ W2r) {
    int i = blockIdx.x * blockDim.x + threadIdx.x;
    if (i < N_NODES * 32) {
        float4 v = x[i];
        __half2* d = (__half2*)(g_xh + i * 4);
        d[0] = __floats2half2_rn(v.x, v.y);
        d[1] = __floats2half2_rn(v.z, v.w);
        return;
    }
    int j = i - N_NODES * 32;
    if (j < N_NODES) { g_cnt[j] = 0; return; }
    int w = j - N_NODES;
    if (w < 256 * 256) {
        int n = w >> 8, k = w & 255;
        g_W1h[w] = __float2half_rn((k < 128) ? W1l[n * 128 + k] : W1r[n * 128 + (k - 128)]);
        g_W2h[w] = __float2half_rn((n < 128) ? W2l[n * 256 + k] : W2r[(n - 128) * 256 + k]);
    }
}

// ================= CSR build =================
__global__ void hist_kernel(const int* __restrict__ ei, int E) {
    int e = blockIdx.x * blockDim.x + threadIdx.x;
    if (e < E) atomicAdd(&g_cnt[ei[E + e]], 1);
}
__global__ __launch_bounds__(1024) void scan1() {
    __shared__ int wsum[32];
    int t = threadIdx.x, lane = t & 31, wid = t >> 5;
    int base = blockIdx.x * SCAN_CHUNK + t * 4;
    int v0 = 0, v1 = 0, v2 = 0, v3 = 0;
    if (base + 3 < N_NODES) {
        int4 v = *(const int4*)(g_cnt + base);
        v0 = v.x; v1 = v.y; v2 = v.z; v3 = v.w;
    } else {
        if (base + 0 < N_NODES) v0 = g_cnt[base + 0];
        if (base + 1 < N_NODES) v1 = g_cnt[base + 1];
        if (base + 2 < N_NODES) v2 = g_cnt[base + 2];
        if (base + 3 < N_NODES) v3 = g_cnt[base + 3];
    }
    int s = v0 + v1 + v2 + v3;
    int inc = s;
#pragma unroll
    for (int off = 1; off < 32; off <<= 1) {
        int n = __shfl_up_sync(0xffffffff, inc, off);
        if (lane >= off) inc += n;
    }
    if (lane == 31) wsum[wid] = inc;
    __syncthreads();
    if (wid == 0) {
        int w = wsum[lane];
#pragma unroll
        for (int off = 1; off < 32; off <<= 1) {
            int n = __shfl_up_sync(0xffffffff, w, off);
            if (lane >= off) w += n;
        }
        wsum[lane] = w;
    }
    __syncthreads();
    int excl = inc - s + (wid > 0 ? wsum[wid - 1] : 0);
    if (base + 0 < N_NODES) g_rowptr[base + 0] = excl;       excl += v0;
    if (base + 1 < N_NODES) g_rowptr[base + 1] = excl;       excl += v1;
    if (base + 2 < N_NODES) g_rowptr[base + 2] = excl;       excl += v2;
    if (base + 3 < N_NODES) g_rowptr[base + 3] = excl;
    if (t == 0) g_bsum[blockIdx.x] = wsum[31];
}
__global__ void scan2() {
    int lane = threadIdx.x;
    int v = (lane < NB_SCAN) ? g_bsum[lane] : 0;
    int inc = v;
#pragma unroll
    for (int off = 1; off < 32; off <<= 1) {
        int n = __shfl_up_sync(0xffffffff, inc, off);
        if (lane >= off) inc += n;
    }
    if (lane < NB_SCAN) g_boff[lane] = inc - v;
}
__global__ void scan3(int E) {
    int i = blockIdx.x * blockDim.x + threadIdx.x;
    if (i < N_NODES) {
        int r = g_rowptr[i] + g_boff[i / SCAN_CHUNK];
        g_rowptr[i] = r;
        g_fill[i] = r;
    }
    if (i == 0) g_rowptr[N_NODES] = E;
}
__global__ void fill_kernel(const int* __restrict__ ei, int E) {
    int e = blockIdx.x * blockDim.x + threadIdx.x;
    if (e >= E) return;
    int s = ei[e];
    int d = ei[E + e];
    int pos = atomicAdd(&g_fill[d], 1);
    g_eidx[pos] = s;
}

// ================= gather-side aggregation (fp16 payload, fp32 accum) =================
__device__ __forceinline__ void acc_u2(float4& acc, uint2 u) {
    float2 f0 = __half22float2(*(__half2*)&u.x);
    float2 f1 = __half22float2(*(__half2*)&u.y);
    acc.x += f0.x; acc.y += f0.y; acc.z += f1.x; acc.w += f1.y;
}

template <int FINAL>
__global__ void agg_gather(const float* __restrict__ b2, float4* __restrict__ out) {
    int node = blockIdx.x * 8 + (threadIdx.x >> 5);
    int lane = threadIdx.x & 31;
    if (node >= N_NODES) return;
    int row = g_rowptr[node], end = g_rowptr[node + 1];
    const uint2* feat = (const uint2*)(FINAL ? g_ph : g_xh);   // [node*32 + lane]
    float4 acc = make_float4(0.f, 0.f, 0.f, 0.f);
    int j = row;
    for (; j + 4 <= end; j += 4) {
        int s0 = __ldg(g_eidx + j), s1 = __ldg(g_eidx + j + 1);
        int s2 = __ldg(g_eidx + j + 2), s3 = __ldg(g_eidx + j + 3);
        acc_u2(acc, feat[s0 * 32 + lane]);
        acc_u2(acc, feat[s1 * 32 + lane]);
        acc_u2(acc, feat[s2 * 32 + lane]);
        acc_u2(acc, feat[s3 * 32 + lane]);
    }
    for (; j < end; j++) {
        int s = __ldg(g_eidx + j);
        acc_u2(acc, feat[s * 32 + lane]);
    }
    float invd = 1.0f / fmaxf((float)(end - row), 1.0f);
    acc.x *= invd; acc.y *= invd; acc.z *= invd; acc.w *= invd;
    if (FINAL) {
        float4 r = g_r2[node * 32 + lane];
        float4 bb = ((const float4*)b2)[lane];
        float4 o;
        o.x = acc.x + bb.x + r.x;
        o.y = acc.y + bb.y + r.y;
        o.z = acc.z + bb.z + r.z;
        o.w = acc.w + bb.w + r.w;
        out[node * 32 + lane] = o;
    } else {
        __half2* d = (__half2*)(g_aggh + node * 128 + lane * 4);
        d[0] = __floats2half2_rn(acc.x, acc.y);
        d[1] = __floats2half2_rn(acc.z, acc.w);
    }
}

// ================= FP16 tensor-core fused double-GEMM =================
#define SA_H 264
#define SB_H 72
#define SA_HALFS (64 * SA_H)
#define SB_HALFS (256 * SB_H)
#define SMEM_BYTES ((SA_HALFS + 2 * SB_HALFS) * 2)

__device__ __forceinline__ void cp16h(__half* dst, const __half* src) {
    uint32_t sa = (uint32_t)__cvta_generic_to_shared(dst);
    asm volatile("cp.async.ca.shared.global [%0], [%1], 16;" :: "r"(sa), "l"(src));
}
__device__ __forceinline__ void cp_commit() { asm volatile("cp.async.commit_group;"); }
__device__ __forceinline__ void cp_wait0()  { asm volatile("cp.async.wait_group 0;"); }

__device__ __forceinline__ void load_chunkB(__half* buf, const __half* Wg, int kc, int tid) {
#pragma unroll
    for (int i = 0; i < 8; i++) {
        int idx = tid + i * 256;
        int n = idx >> 3, c8 = idx & 7;
        cp16h(buf + n * SB_H + c8 * 8, Wg + n * 256 + kc * 64 + c8 * 8);
    }
}

__device__ __forceinline__ void mma_f16(float* d, uint32_t a0, uint32_t a1, uint32_t a2,
                                        uint32_t a3, uint32_t b0, uint32_t b1) {
    asm volatile(
        "mma.sync.aligned.m16n8k16.row.col.f32.f16.f16.f32 "
        "{%0,%1,%2,%3}, {%4,%5,%6,%7}, {%8,%9}, {%0,%1,%2,%3};"
        : "+f"(d[0]), "+f"(d[1]), "+f"(d[2]), "+f"(d[3])
        : "r"(a0), "r"(a1), "r"(a2), "r"(a3), "r"(b0), "r"(b1));
}

// one 256-K fp16 GEMM: acc += A(64x256 smem) @ Wg(256n x 256k, row=n)^T
__device__ __forceinline__ void gemm_fp16(const __half* A, const __half* Wg, const __half* WgNext,
                                          __half* sB0, __half* sB1,
                                          float acc[4][4][4], int tid, int lane, int n_base) {
    __half* sb[2] = {sB0, sB1};
    for (int kc = 0; kc < 4; kc++) {
        cp_wait0();
        __syncthreads();
        if (kc < 3)      { load_chunkB(sb[(kc + 1) & 1], Wg, kc + 1, tid); cp_commit(); }
        else if (WgNext) { load_chunkB(sb[0], WgNext, 0, tid); cp_commit(); }
        const __half* B = sb[kc & 1];
#pragma unroll
        for (int ksl = 0; ksl < 4; ksl++) {
            // B frags for 4 n8-tiles via 2 ldmatrix.x4 (lanes 16-31 address the 2nd tile)
            uint32_t bf[4][2];
#pragma unroll
            for (int np = 0; np < 2; np++) {
                int n = n_base + np * 16 + ((lane >> 4) << 3) + (lane & 7);
                int kl = ksl * 16 + ((lane >> 3) & 1) * 8;
                uint32_t ad = (uint32_t)__cvta_generic_to_shared(B + n * SB_H + kl);
                asm volatile("ldmatrix.sync.aligned.m8n8.x4.shared.b16 {%0,%1,%2,%3}, [%4];"
                             : "=r"(bf[np * 2][0]), "=r"(bf[np * 2][1]),
                               "=r"(bf[np * 2 + 1][0]), "=r"(bf[np * 2 + 1][1]) : "r"(ad));
            }
#pragma unroll
            for (int mt = 0; mt < 4; mt++) {
                int m = mt * 16 + (lane & 15);
                int kk = kc * 64 + ksl * 16 + (lane >> 4) * 8;
                uint32_t ad = (uint32_t)__cvta_generic_to_shared(A + m * SA_H + kk);
                uint32_t a0, a1, a2, a3;
                asm volatile("ldmatrix.sync.aligned.m8n8.x4.shared.b16 {%0,%1,%2,%3}, [%4];"
                             : "=r"(a0), "=r"(a1), "=r"(a2), "=r"(a3) : "r"(ad));
#pragma unroll
                for (int nt = 0; nt < 4; nt++)
                    mma_f16(acc[mt][nt], a0, a1, a2, a3, bf[nt][0], bf[nt][1]);
            }
        }
    }
}

__global__ __launch_bounds__(256, 2) void gemm_mma_h(const float* __restrict__ b1) {
    extern __shared__ __half smem_h[];
    __half* sA  = smem_h;
    __half* sB0 = smem_h + SA_HALFS;
    __half* sB1 = sB0 + SB_HALFS;

    int tid = threadIdx.x, lane = tid & 31, warp = tid >> 5;
    int node0 = blockIdx.x * 64;
    int n_base = warp * 32;

    load_chunkB(sB0, g_W1h, 0, tid);
#pragma unroll
    for (int i = 0; i < 8; i++) {
        int idx = tid + i * 256;
        int n = idx >> 5, c8 = idx & 31;
        int node = node0 + n;
        if (node >= N_NODES) node = N_NODES - 1;
        const __half* src = (c8 < 16) ? (g_aggh + node * 128 + c8 * 8)
                                      : (g_xh  + node * 128 + (c8 - 16) * 8);
        cp16h(sA + n * SA_H + c8 * 8, src);
    }
    cp_commit();

    float acc[4][4][4];
#pragma unroll
    for (int a = 0; a < 4; a++)
#pragma unroll
        for (int b = 0; b < 4; b++)
#pragma unroll
            for (int c = 0; c < 4; c++) acc[a][b][c] = 0.f;

    gemm_fp16(sA, g_W1h, g_W2h, sB0, sB1, acc, tid, lane, n_base);

    __syncthreads();

#pragma unroll
    for (int mt = 0; mt < 4; mt++) {
        int row = mt * 16 + (lane >> 2);
#pragma unroll
        for (int nt = 0; nt < 4; nt++) {
            int col = n_base + nt * 8 + (lane & 3) * 2;
            float bb0 = __ldg(b1 + col), bb1 = __ldg(b1 + col + 1);
            *(__half2*)(sA + row * SA_H + col) =
                __floats2half2_rn(fmaxf(acc[mt][nt][0] + bb0, 0.f),
                                  fmaxf(acc[mt][nt][1] + bb1, 0.f));
            *(__half2*)(sA + (row + 8) * SA_H + col) =
                __floats2half2_rn(fmaxf(acc[mt][nt][2] + bb0, 0.f),
                                  fmaxf(acc[mt][nt][3] + bb1, 0.f));
            acc[mt][nt][0] = acc[mt][nt][1] = acc[mt][nt][2] = acc[mt][nt][3] = 0.f;
        }
    }

    gemm_fp16(sA, g_W2h, nullptr, sB0, sB1, acc, tid, lane, n_base);

    float* gr = (float*)g_r2;
#pragma unroll
    for (int mt = 0; mt < 4; mt++) {
        int row = mt * 16 + (lane >> 2);
#pragma unroll
        for (int nt = 0; nt < 4; nt++) {
            int col = n_base + nt * 8 + (lane & 3) * 2;
            int node = node0 + row;
            if (col < 128) {
                if (node < N_NODES)
                    *(__half2*)(g_ph + node * 128 + col) =
                        __floats2half2_rn(acc[mt][nt][0], acc[mt][nt][1]);
                if (node + 8 < N_NODES)
                    *(__half2*)(g_ph + (node + 8) * 128 + col) =
                        __floats2half2_rn(acc[mt][nt][2], acc[mt][nt][3]);
            } else {
                int cc = col - 128;
                if (node < N_NODES)
                    *(float2*)(gr + node * 128 + cc) = make_float2(acc[mt][nt][0], acc[mt][nt][1]);
                if (node + 8 < N_NODES)
                    *(float2*)(gr + (node + 8) * 128 + cc) = make_float2(acc[mt][nt][2], acc[mt][nt][3]);
            }
        }
    }
}

extern "C" void kernel_launch(void* const* d_in, const int* in_sizes, int n_in,
                              void* d_out, int out_size) {
    const float4* x   = (const float4*)d_in[0];
    const int*    ei  = (const int*)d_in[1];
    const float*  W1l = (const float*)d_in[2];
    const float*  b1  = (const float*)d_in[3];
    const float*  W1r = (const float*)d_in[4];
    const float*  W2l = (const float*)d_in[5];
    const float*  b2  = (const float*)d_in[6];
    const float*  W2r = (const float*)d_in[7];
    int E = in_sizes[1] / 2;

    cudaFuncSetAttribute(gemm_mma_h, cudaFuncAttributeMaxDynamicSharedMemorySize, SMEM_BYTES);

    prep_all<<<(PREP_TOTAL + 255) / 256, 256>>>(x, W1l, W1r, W2l, W2r);
    hist_kernel<<<(E + 255) / 256, 256>>>(ei, E);
    scan1<<<NB_SCAN, 1024>>>();
    scan2<<<1, 32>>>();
    scan3<<<(N_NODES + 255) / 256, 256>>>(E);
    fill_kernel<<<(E + 255) / 256, 256>>>(ei, E);
    agg_gather<0><<<(N_NODES + 7) / 8, 256>>>(nullptr, nullptr);
    gemm_mma_h<<<(N_NODES + 63) / 64, 256, SMEM_BYTES>>>(b1);
    agg_gather<1><<<(N_NODES + 7) / 8, 256>>>(b2, (float4*)d_out);
}

// round 12
// speedup vs baseline: 6.2392x; 1.0106x over previous
#include <cuda_runtime.h>
#include <cuda_fp16.h>
#include <cstdint>

#define N_NODES 50000
#define E_MAX   800000
#define SCAN_CHUNK 4096
#define NB_SCAN ((N_NODES + SCAN_CHUNK - 1) / SCAN_CHUNK)   // 13

// ---- scratch (static __device__ — no allocations allowed) ----
__device__ __align__(16) __half g_xh  [N_NODES * 128];  // x in fp16
__device__ __align__(16) __half g_aggh[N_NODES * 128];  // MEAN of x[src] per dst (fp16)
__device__ __align__(16) __half g_ph  [N_NODES * 128];  // h @ W2_l.T  (fp16)
__device__ __align__(16) __half g_r2h [N_NODES * 128];  // h @ W2_r.T  (fp16)
__device__ __align__(16) __half g_W1h [256 * 256];      // [t][k] fp16
__device__ __align__(16) __half g_W2h [256 * 256];      // [j][k] fp16
// CSR by dst
__device__ __align__(16) int g_cnt [N_NODES];
__device__ int g_fill[N_NODES];
__device__ int g_rowptr[N_NODES + 1];
__device__ int g_eidx[E_MAX];
__device__ int g_bsum[NB_SCAN];

// ================= fused prep: zero cnt + x->fp16 + weights->fp16 =================
#define PREP_TOTAL (N_NODES * 32 + N_NODES + 256 * 256)
__global__ void prep_all(const float4* __restrict__ x,
                         const float* __restrict__ W1l, const float* __restrict__ W1r,
                         const float* __restrict__ W2l, const float* __restrict__ W2r) {
    int i = blockIdx.x * blockDim.x + threadIdx.x;
    if (i < N_NODES * 32) {
        float4 v = x[i];
        __half2* d = (__half2*)(g_xh + i * 4);
        d[0] = __floats2half2_rn(v.x, v.y);
        d[1] = __floats2half2_rn(v.z, v.w);
        return;
    }
    int j = i - N_NODES * 32;
    if (j < N_NODES) { g_cnt[j] = 0; return; }
    int w = j - N_NODES;
    if (w < 256 * 256) {
        int n = w >> 8, k = w & 255;
        g_W1h[w] = __float2half_rn((k < 128) ? W1l[n * 128 + k] : W1r[n * 128 + (k - 128)]);
        g_W2h[w] = __float2half_rn((n < 128) ? W2l[n * 256 + k] : W2r[(n - 128) * 256 + k]);
    }
}

// ================= CSR build =================
__global__ void hist_kernel(const int* __restrict__ ei, int E) {
    int e = blockIdx.x * blockDim.x + threadIdx.x;
    if (e < E) atomicAdd(&g_cnt[ei[E + e]], 1);
}
__global__ __launch_bounds__(1024) void scan1() {
    __shared__ int wsum[32];
    int t = threadIdx.x, lane = t & 31, wid = t >> 5;
    int base = blockIdx.x * SCAN_CHUNK + t * 4;
    int v0 = 0, v1 = 0, v2 = 0, v3 = 0;
    if (base + 3 < N_NODES) {
        int4 v = *(const int4*)(g_cnt + base);
        v0 = v.x; v1 = v.y; v2 = v.z; v3 = v.w;
    } else {
        if (base + 0 < N_NODES) v0 = g_cnt[base + 0];
        if (base + 1 < N_NODES) v1 = g_cnt[base + 1];
        if (base + 2 < N_NODES) v2 = g_cnt[base + 2];
        if (base + 3 < N_NODES) v3 = g_cnt[base + 3];
    }
    int s = v0 + v1 + v2 + v3;
    int inc = s;
#pragma unroll
    for (int off = 1; off < 32; off <<= 1) {
        int n = __shfl_up_sync(0xffffffff, inc, off);
        if (lane >= off) inc += n;
    }
    if (lane == 31) wsum[wid] = inc;
    __syncthreads();
    if (wid == 0) {
        int w = wsum[lane];
#pragma unroll
        for (int off = 1; off < 32; off <<= 1) {
            int n = __shfl_up_sync(0xffffffff, w, off);
            if (lane >= off) w += n;
        }
        wsum[lane] = w;
    }
    __syncthreads();
    int excl = inc - s + (wid > 0 ? wsum[wid - 1] : 0);
    if (base + 0 < N_NODES) g_rowptr[base + 0] = excl;       excl += v0;
    if (base + 1 < N_NODES) g_rowptr[base + 1] = excl;       excl += v1;
    if (base + 2 < N_NODES) g_rowptr[base + 2] = excl;       excl += v2;
    if (base + 3 < N_NODES) g_rowptr[base + 3] = excl;
    if (t == 0) g_bsum[blockIdx.x] = wsum[31];
}
// scan3: inline 13-element block-total prefix (warp 0), then add offsets
__global__ void scan3(int E) {
    __shared__ int sboff[NB_SCAN];
    int t = threadIdx.x;
    if (t < 32) {
        int v = (t < NB_SCAN) ? g_bsum[t] : 0;
        int inc = v;
#pragma unroll
        for (int off = 1; off < 32; off <<= 1) {
            int n = __shfl_up_sync(0xffffffff, inc, off);
            if (t >= off) inc += n;
        }
        if (t < NB_SCAN) sboff[t] = inc - v;
    }
    __syncthreads();
    int i = blockIdx.x * blockDim.x + t;
    if (i < N_NODES) {
        int r = g_rowptr[i] + sboff[i / SCAN_CHUNK];
        g_rowptr[i] = r;
        g_fill[i] = r;
    }
    if (i == 0) g_rowptr[N_NODES] = E;
}
__global__ void fill_kernel(const int* __restrict__ ei, int E) {
    int e = blockIdx.x * blockDim.x + threadIdx.x;
    if (e >= E) return;
    int s = ei[e];
    int d = ei[E + e];
    int pos = atomicAdd(&g_fill[d], 1);
    g_eidx[pos] = s;
}

// ================= gather-side aggregation (fp16 payload, fp32 accum) =================
__device__ __forceinline__ void acc_u2(float4& acc, uint2 u) {
    float2 f0 = __half22float2(*(__half2*)&u.x);
    float2 f1 = __half22float2(*(__half2*)&u.y);
    acc.x += f0.x; acc.y += f0.y; acc.z += f1.x; acc.w += f1.y;
}

template <int FINAL>
__global__ void agg_gather(const float* __restrict__ b2, float4* __restrict__ out) {
    int node = blockIdx.x * 8 + (threadIdx.x >> 5);
    int lane = threadIdx.x & 31;
    if (node >= N_NODES) return;
    int row = g_rowptr[node], end = g_rowptr[node + 1];
    const uint2* feat = (const uint2*)(FINAL ? g_ph : g_xh);   // [node*32 + lane]
    float4 acc = make_float4(0.f, 0.f, 0.f, 0.f);
    int j = row;
    for (; j + 4 <= end; j += 4) {
        int s0 = __ldg(g_eidx + j), s1 = __ldg(g_eidx + j + 1);
        int s2 = __ldg(g_eidx + j + 2), s3 = __ldg(g_eidx + j + 3);
        acc_u2(acc, feat[s0 * 32 + lane]);
        acc_u2(acc, feat[s1 * 32 + lane]);
        acc_u2(acc, feat[s2 * 32 + lane]);
        acc_u2(acc, feat[s3 * 32 + lane]);
    }
    for (; j < end; j++) {
        int s = __ldg(g_eidx + j);
        acc_u2(acc, feat[s * 32 + lane]);
    }
    float invd = 1.0f / fmaxf((float)(end - row), 1.0f);
    acc.x *= invd; acc.y *= invd; acc.z *= invd; acc.w *= invd;
    if (FINAL) {
        uint2 ru = ((const uint2*)g_r2h)[node * 32 + lane];
        float2 r0 = __half22float2(*(__half2*)&ru.x);
        float2 r1 = __half22float2(*(__half2*)&ru.y);
        float4 bb = ((const float4*)b2)[lane];
        float4 o;
        o.x = acc.x + bb.x + r0.x;
        o.y = acc.y + bb.y + r0.y;
        o.z = acc.z + bb.z + r1.x;
        o.w = acc.w + bb.w + r1.y;
        out[node * 32 + lane] = o;
    } else {
        __half2* d = (__half2*)(g_aggh + node * 128 + lane * 4);
        d[0] = __floats2half2_rn(acc.x, acc.y);
        d[1] = __floats2half2_rn(acc.z, acc.w);
    }
}

// ================= FP16 tensor-core fused double-GEMM =================
#define SA_H 264
#define SB_H 72
#define SA_HALFS (64 * SA_H)
#define SB_HALFS (256 * SB_H)
#define SMEM_BYTES ((SA_HALFS + 2 * SB_HALFS) * 2)

__device__ __forceinline__ void cp16h(__half* dst, const __half* src) {
    uint32_t sa = (uint32_t)__cvta_generic_to_shared(dst);
    asm volatile("cp.async.ca.shared.global [%0], [%1], 16;" :: "r"(sa), "l"(src));
}
__device__ __forceinline__ void cp_commit() { asm volatile("cp.async.commit_group;"); }
__device__ __forceinline__ void cp_wait0()  { asm volatile("cp.async.wait_group 0;"); }

__device__ __forceinline__ void load_chunkB(__half* buf, const __half* Wg, int kc, int tid) {
#pragma unroll
    for (int i = 0; i < 8; i++) {
        int idx = tid + i * 256;
        int n = idx >> 3, c8 = idx & 7;
        cp16h(buf + n * SB_H + c8 * 8, Wg + n * 256 + kc * 64 + c8 * 8);
    }
}

__device__ __forceinline__ void mma_f16(float* d, uint32_t a0, uint32_t a1, uint32_t a2,
                                        uint32_t a3, uint32_t b0, uint32_t b1) {
    asm volatile(
        "mma.sync.aligned.m16n8k16.row.col.f32.f16.f16.f32 "
        "{%0,%1,%2,%3}, {%4,%5,%6,%7}, {%8,%9}, {%0,%1,%2,%3};"
        : "+f"(d[0]), "+f"(d[1]), "+f"(d[2]), "+f"(d[3])
        : "r"(a0), "r"(a1), "r"(a2), "r"(a3), "r"(b0), "r"(b1));
}

// one 256-K fp16 GEMM: acc += A(64x256 smem) @ Wg(256n x 256k, row=n)^T
__device__ __forceinline__ void gemm_fp16(const __half* A, const __half* Wg, const __half* WgNext,
                                          __half* sB0, __half* sB1,
                                          float acc[4][4][4], int tid, int lane, int n_base) {
    __half* sb[2] = {sB0, sB1};
    for (int kc = 0; kc < 4; kc++) {
        cp_wait0();
        __syncthreads();
        if (kc < 3)      { load_chunkB(sb[(kc + 1) & 1], Wg, kc + 1, tid); cp_commit(); }
        else if (WgNext) { load_chunkB(sb[0], WgNext, 0, tid); cp_commit(); }
        const __half* B = sb[kc & 1];
#pragma unroll
        for (int ksl = 0; ksl < 4; ksl++) {
            uint32_t bf[4][2];
#pragma unroll
            for (int np = 0; np < 2; np++) {
                int n = n_base + np * 16 + ((lane >> 4) << 3) + (lane & 7);
                int kl = ksl * 16 + ((lane >> 3) & 1) * 8;
                uint32_t ad = (uint32_t)__cvta_generic_to_shared(B + n * SB_H + kl);
                asm volatile("ldmatrix.sync.aligned.m8n8.x4.shared.b16 {%0,%1,%2,%3}, [%4];"
                             : "=r"(bf[np * 2][0]), "=r"(bf[np * 2][1]),
                               "=r"(bf[np * 2 + 1][0]), "=r"(bf[np * 2 + 1][1]) : "r"(ad));
            }
#pragma unroll
            for (int mt = 0; mt < 4; mt++) {
                int m = mt * 16 + (lane & 15);
                int kk = kc * 64 + ksl * 16 + (lane >> 4) * 8;
                uint32_t ad = (uint32_t)__cvta_generic_to_shared(A + m * SA_H + kk);
                uint32_t a0, a1, a2, a3;
                asm volatile("ldmatrix.sync.aligned.m8n8.x4.shared.b16 {%0,%1,%2,%3}, [%4];"
                             : "=r"(a0), "=r"(a1), "=r"(a2), "=r"(a3) : "r"(ad));
#pragma unroll
                for (int nt = 0; nt < 4; nt++)
                    mma_f16(acc[mt][nt], a0, a1, a2, a3, bf[nt][0], bf[nt][1]);
            }
        }
    }
}

__global__ __launch_bounds__(256, 2) void gemm_mma_h(const float* __restrict__ b1) {
    extern __shared__ __half smem_h[];
    __half* sA  = smem_h;
    __half* sB0 = smem_h + SA_HALFS;
    __half* sB1 = sB0 + SB_HALFS;

    int tid = threadIdx.x, lane = tid & 31, warp = tid >> 5;
    int node0 = blockIdx.x * 64;
    int n_base = warp * 32;

    load_chunkB(sB0, g_W1h, 0, tid);
#pragma unroll
    for (int i = 0; i < 8; i++) {
        int idx = tid + i * 256;
        int n = idx >> 5, c8 = idx & 31;
        int node = node0 + n;
        if (node >= N_NODES) node = N_NODES - 1;
        const __half* src = (c8 < 16) ? (g_aggh + node * 128 + c8 * 8)
                                      : (g_xh  + node * 128 + (c8 - 16) * 8);
        cp16h(sA + n * SA_H + c8 * 8, src);
    }
    cp_commit();

    float acc[4][4][4];
#pragma unroll
    for (int a = 0; a < 4; a++)
#pragma unroll
        for (int b = 0; b < 4; b++)
#pragma unroll
            for (int c = 0; c < 4; c++) acc[a][b][c] = 0.f;

    gemm_fp16(sA, g_W1h, g_W2h, sB0, sB1, acc, tid, lane, n_base);

    __syncthreads();

#pragma unroll
    for (int mt = 0; mt < 4; mt++) {
        int row = mt * 16 + (lane >> 2);
#pragma unroll
        for (int nt = 0; nt < 4; nt++) {
            int col = n_base + nt * 8 + (lane & 3) * 2;
            float bb0 = __ldg(b1 + col), bb1 = __ldg(b1 + col + 1);
            *(__half2*)(sA + row * SA_H + col) =
                __floats2half2_rn(fmaxf(acc[mt][nt][0] + bb0, 0.f),
                                  fmaxf(acc[mt][nt][1] + bb1, 0.f));
            *(__half2*)(sA + (row + 8) * SA_H + col) =
                __floats2half2_rn(fmaxf(acc[mt][nt][2] + bb0, 0.f),
                                  fmaxf(acc[mt][nt][3] + bb1, 0.f));
            acc[mt][nt][0] = acc[mt][nt][1] = acc[mt][nt][2] = acc[mt][nt][3] = 0.f;
        }
    }

    gemm_fp16(sA, g_W2h, nullptr, sB0, sB1, acc, tid, lane, n_base);

    // store p (cols<128) and r2 (cols>=128) both as fp16
#pragma unroll
    for (int mt = 0; mt < 4; mt++) {
        int row = mt * 16 + (lane >> 2);
#pragma unroll
        for (int nt = 0; nt < 4; nt++) {
            int col = n_base + nt * 8 + (lane & 3) * 2;
            int node = node0 + row;
            __half* base = (col < 128) ? g_ph : g_r2h;
            int cc = col & 127;
            if (node < N_NODES)
                *(__half2*)(base + node * 128 + cc) =
                    __floats2half2_rn(acc[mt][nt][0], acc[mt][nt][1]);
            if (node + 8 < N_NODES)
                *(__half2*)(base + (node + 8) * 128 + cc) =
                    __floats2half2_rn(acc[mt][nt][2], acc[mt][nt][3]);
        }
    }
}

extern "C" void kernel_launch(void* const* d_in, const int* in_sizes, int n_in,
                              void* d_out, int out_size) {
    const float4* x   = (const float4*)d_in[0];
    const int*    ei  = (const int*)d_in[1];
    const float*  W1l = (const float*)d_in[2];
    const float*  b1  = (const float*)d_in[3];
    const float*  W1r = (const float*)d_in[4];
    const float*  W2l = (const float*)d_in[5];
    const float*  b2  = (const float*)d_in[6];
    const float*  W2r = (const float*)d_in[7];
    int E = in_sizes[1] / 2;

    cudaFuncSetAttribute(gemm_mma_h, cudaFuncAttributeMaxDynamicSharedMemorySize, SMEM_BYTES);

    prep_all<<<(PREP_TOTAL + 255) / 256, 256>>>(x, W1l, W1r, W2l, W2r);
    hist_kernel<<<(E + 255) / 256, 256>>>(ei, E);
    scan1<<<NB_SCAN, 1024>>>();
    scan3<<<(N_NODES + 255) / 256, 256>>>(E);
    fill_kernel<<<(E + 255) / 256, 256>>>(ei, E);
    agg_gather<0><<<(N_NODES + 7) / 8, 256>>>(nullptr, nullptr);
    gemm_mma_h<<<(N_NODES + 63) / 64, 256, SMEM_BYTES>>>(b1);
    agg_gather<1><<<(N_NODES + 7) / 8, 256>>>(b2, (float4*)d_out);
}